// round 3
// baseline (speedup 1.0000x reference)
#include <cuda_runtime.h>
#include <cstdint>
#include <math.h>

static constexpr int NN = 8192;
static constexpr int FF = 256;
static constexpr int EE = 262144;
static constexpr float C_ALPHA  = 0.9f;
static constexpr float C_EPS    = 0.01f;
static constexpr float C_THRESH = 0.8f;
static constexpr float C_COSEPS = 1e-8f;

// ------------------------- device scratch (no runtime alloc allowed) -------
__device__ float    g_mean[FF];            // column sums, later /N
__device__ float    g_G[FF * FF];          // z^T z
__device__ float    g_cor[FF * FF];
__device__ float    g_w[NN];
__device__ float    g_z2[NN * FF];
__device__ float    g_inorm[NN];
__device__ float    g_scores[NN];
__device__ float    g_deg[NN];
__device__ unsigned g_adj[NN * NN / 32];   // 8 MB bitmask
__device__ int      g_ei[EE];
__device__ int      g_ej[EE];
__device__ double   g_psum;
__device__ int      g_flag_e, g_flag_k, g_flag_u;   // 1 => int64 input

__device__ __forceinline__ float warp_red(float v) {
    #pragma unroll
    for (int o = 16; o; o >>= 1) v += __shfl_xor_sync(0xffffffffu, v, o);
    return v;
}

// ------------------------- zeroing --------------------------------------
__global__ void k_zero() {
    int idx = blockIdx.x * blockDim.x + threadIdx.x;
    int stride = gridDim.x * blockDim.x;
    for (int i = idx; i < NN * NN / 32; i += stride) g_adj[i] = 0u;
    for (int i = idx; i < FF * FF; i += stride) g_G[i] = 0.0f;
    for (int i = idx; i < NN; i += stride) { g_scores[i] = 0.0f; g_deg[i] = 0.0f; }
    for (int i = idx; i < FF; i += stride) g_mean[i] = 0.0f;
    if (idx == 0) g_psum = 0.0;
}

// ------------------------- dtype detection ------------------------------
__device__ __forceinline__ int detect64(const void* p, long long bound) {
    const long long* q = (const long long*)p;
    int c = 0;
    for (int s = 0; s < 64; s++) {
        long long v = q[s];
        if (v >= 0 && v < bound) c++;
    }
    return c >= 60 ? 1 : 0;
}

__global__ void k_detect(const void* ep, const void* kp, const void* up) {
    if (threadIdx.x == 0) g_flag_e = detect64(ep, NN);
    else if (threadIdx.x == 1) g_flag_k = detect64(kp, 6);
    else if (threadIdx.x == 2) g_flag_u = detect64(up, 32);
}

__global__ void k_convert(const void* ep) {
    int e = blockIdx.x * blockDim.x + threadIdx.x;
    if (e >= EE) return;
    if (g_flag_e) {
        const long long* p = (const long long*)ep;
        g_ei[e] = (int)p[e];
        g_ej[e] = (int)p[EE + e];
    } else {
        const int* p = (const int*)ep;
        g_ei[e] = p[e];
        g_ej[e] = p[EE + e];
    }
}

__global__ void k_wcalc(const void* kp, const void* up) {
    int n = blockIdx.x * blockDim.x + threadIdx.x;
    if (n >= NN) return;
    float fk, fu;
    if (g_flag_k) fk = (float)((const long long*)kp)[n];
    else          fk = (float)((const int*)kp)[n];
    if (g_flag_u) fu = (float)((const long long*)up)[n];
    else          fu = (float)((const int*)up)[n];
    g_w[n] = powf(C_ALPHA, fk) + 1.0f - powf(C_ALPHA, fu);
}

// ------------------------- column sums (means) --------------------------
__global__ void k_colsum(const float* __restrict__ z) {
    int t = threadIdx.x;                 // feature column
    int r0 = blockIdx.x * 128;           // 64 blocks x 128 rows
    float acc = 0.0f;
    for (int m = 0; m < 128; m++) acc += z[(r0 + m) * FF + t];
    atomicAdd(&g_mean[t], acc);
}

// ------------------------- Gram matrix G = z^T z (split-K) --------------
__global__ void k_gram(const float* __restrict__ z) {
    __shared__ float As[8][64];
    __shared__ float Bs[8][64];
    // decode tile pair ti<=tj among 4 tiles of 64
    int p = blockIdx.x, ti = 0;
    while (p >= 4 - ti) { p -= 4 - ti; ti++; }
    int tj = ti + p;
    int i0 = ti * 64, j0 = tj * 64;
    int k0 = blockIdx.y * 256;
    int tid = threadIdx.x;
    int tx = tid & 15, ty = tid >> 4;
    float c[4][4];
    #pragma unroll
    for (int a = 0; a < 4; a++)
        #pragma unroll
        for (int b = 0; b < 4; b++) c[a][b] = 0.0f;

    for (int ks = 0; ks < 256; ks += 8) {
        int f2 = tid * 2;
        int kk = f2 >> 6, cc = f2 & 63;
        As[kk][cc]     = z[(k0 + ks + kk) * FF + i0 + cc];
        As[kk][cc + 1] = z[(k0 + ks + kk) * FF + i0 + cc + 1];
        Bs[kk][cc]     = z[(k0 + ks + kk) * FF + j0 + cc];
        Bs[kk][cc + 1] = z[(k0 + ks + kk) * FF + j0 + cc + 1];
        __syncthreads();
        #pragma unroll
        for (int q = 0; q < 8; q++) {
            float4 av = *(const float4*)&As[q][ty * 4];
            float4 bv = *(const float4*)&Bs[q][tx * 4];
            float aa[4] = {av.x, av.y, av.z, av.w};
            float bb[4] = {bv.x, bv.y, bv.z, bv.w};
            #pragma unroll
            for (int a = 0; a < 4; a++)
                #pragma unroll
                for (int b = 0; b < 4; b++) c[a][b] += aa[a] * bb[b];
        }
        __syncthreads();
    }
    #pragma unroll
    for (int a = 0; a < 4; a++) {
        int gi = i0 + ty * 4 + a;
        #pragma unroll
        for (int b = 0; b < 4; b++) {
            int gj = j0 + tx * 4 + b;
            atomicAdd(&g_G[gi * FF + gj], c[a][b]);
            if (ti != tj) atomicAdd(&g_G[gj * FF + gi], c[a][b]);
        }
    }
}

// ------------------------- correlation matrix ---------------------------
__global__ void k_cor() {
    int i = blockIdx.x, j = threadIdx.x;
    float mi = g_mean[i] / (float)NN;
    float mj = g_mean[j] / (float)NN;
    float cov = g_G[i * FF + j] - (float)NN * mi * mj;
    float vii = g_G[i * FF + i] - (float)NN * mi * mi;
    float vjj = g_G[j * FF + j] - (float)NN * mj * mj;
    float c = cov / (sqrtf(vii) * sqrtf(vjj));
    if (isnan(c)) c = 0.0f;
    c = fminf(fmaxf(c, -1.0f), 1.0f);
    if (i == j) c = 0.0f;
    g_cor[i * FF + j] = c;
}

// ------------------------- z2 = z + eps * w * ((z-mean) @ cor) ----------
__global__ void k_z2(const float* __restrict__ z) {
    __shared__ float xs[32][FF];
    __shared__ float ws[32];
    int tid = threadIdx.x;
    int r0 = blockIdx.x * 32;
    float meanv = g_mean[tid] / (float)NN;
    for (int m = 0; m < 32; m++)
        xs[m][tid] = z[(r0 + m) * FF + tid] - meanv;
    if (tid < 32) ws[tid] = g_w[r0 + tid];
    __syncthreads();

    float acc[32];
    #pragma unroll
    for (int m = 0; m < 32; m++) acc[m] = 0.0f;

    for (int k = 0; k < FF; k += 4) {
        float c0 = g_cor[(k + 0) * FF + tid];
        float c1 = g_cor[(k + 1) * FF + tid];
        float c2 = g_cor[(k + 2) * FF + tid];
        float c3 = g_cor[(k + 3) * FF + tid];
        #pragma unroll
        for (int m = 0; m < 32; m++) {
            float4 xv = *(const float4*)&xs[m][k];
            acc[m] += xv.x * c0 + xv.y * c1 + xv.z * c2 + xv.w * c3;
        }
    }
    #pragma unroll
    for (int m = 0; m < 32; m++) {
        int row = r0 + m;
        g_z2[row * FF + tid] = z[row * FF + tid] + C_EPS * ws[m] * acc[m];
    }
}

// ------------------------- adjacency bitmask ----------------------------
__global__ void k_adj() {
    int e = blockIdx.x * blockDim.x + threadIdx.x;
    if (e >= EE) return;
    int i = g_ei[e], j = g_ej[e];
    atomicOr(&g_adj[(i * NN + j) >> 5], 1u << (j & 31));
    atomicOr(&g_adj[(j * NN + i) >> 5], 1u << (i & 31));
}

// ------------------------- per-node inverse norms -----------------------
__global__ void k_norms() {
    int warp = threadIdx.x >> 5, lane = threadIdx.x & 31;
    int row = blockIdx.x * 8 + warp;
    const float* p = &g_z2[row * FF];
    float4 a = *(const float4*)&p[lane * 4];
    float4 b = *(const float4*)&p[128 + lane * 4];
    float s = a.x * a.x + a.y * a.y + a.z * a.z + a.w * a.w
            + b.x * b.x + b.y * b.y + b.z * b.z + b.w * b.w;
    s = warp_red(s);
    if (lane == 0) g_inorm[row] = 1.0f / fmaxf(sqrtf(s), C_COSEPS);
}

// ------------------------- homophily: warp per edge ---------------------
__global__ void k_edge() {
    int warp = threadIdx.x >> 5, lane = threadIdx.x & 31;
    int e = blockIdx.x * 8 + warp;
    int i = g_ei[e], j = g_ej[e];
    const float* pi = &g_z2[i * FF];
    const float* pj = &g_z2[j * FF];
    float4 a0 = *(const float4*)&pi[lane * 4];
    float4 b0 = *(const float4*)&pj[lane * 4];
    float4 a1 = *(const float4*)&pi[128 + lane * 4];
    float4 b1 = *(const float4*)&pj[128 + lane * 4];
    float d = a0.x * b0.x + a0.y * b0.y + a0.z * b0.z + a0.w * b0.w
            + a1.x * b1.x + a1.y * b1.y + a1.z * b1.z + a1.w * b1.w;
    d = warp_red(d);
    if (lane == 0) {
        float sim = d * g_inorm[i] * g_inorm[j];
        atomicAdd(&g_scores[i], sim);
        atomicAdd(&g_deg[i], 1.0f);
    }
}

// ------------------------- big masked GEMM (symmetric, upper tiles) -----
__global__ __launch_bounds__(256, 2) void k_big() {
    __shared__ float As[16][132];
    __shared__ float Bs[16][132];
    // decode tile pair ti<=tj among 64 tiles of 128
    int p = blockIdx.x, ti = 0;
    while (p >= 64 - ti) { p -= 64 - ti; ti++; }
    int tj = ti + p;
    int i0 = ti * 128, j0 = tj * 128;
    int tid = threadIdx.x;
    int tx = tid & 15, ty = tid >> 4;
    int quad = tid & 3, r = tid >> 2;

    float acc[8][8];
    #pragma unroll
    for (int v = 0; v < 8; v++)
        #pragma unroll
        for (int u = 0; u < 8; u++) acc[v][u] = 0.0f;

    for (int k0 = 0; k0 < FF; k0 += 16) {
        #pragma unroll
        for (int pass = 0; pass < 2; pass++) {
            int rr = r + pass * 64;
            float4 va = *(const float4*)&g_z2[(i0 + rr) * FF + k0 + quad * 4];
            As[quad * 4 + 0][rr] = va.x;
            As[quad * 4 + 1][rr] = va.y;
            As[quad * 4 + 2][rr] = va.z;
            As[quad * 4 + 3][rr] = va.w;
            float4 vb = *(const float4*)&g_z2[(j0 + rr) * FF + k0 + quad * 4];
            Bs[quad * 4 + 0][rr] = vb.x;
            Bs[quad * 4 + 1][rr] = vb.y;
            Bs[quad * 4 + 2][rr] = vb.z;
            Bs[quad * 4 + 3][rr] = vb.w;
        }
        __syncthreads();
        #pragma unroll
        for (int kk = 0; kk < 16; kk++) {
            float4 a0 = *(const float4*)&As[kk][ty * 8];
            float4 a1 = *(const float4*)&As[kk][ty * 8 + 4];
            float4 b0 = *(const float4*)&Bs[kk][tx * 8];
            float4 b1 = *(const float4*)&Bs[kk][tx * 8 + 4];
            float a[8] = {a0.x, a0.y, a0.z, a0.w, a1.x, a1.y, a1.z, a1.w};
            float b[8] = {b0.x, b0.y, b0.z, b0.w, b1.x, b1.y, b1.z, b1.w};
            #pragma unroll
            for (int v = 0; v < 8; v++)
                #pragma unroll
                for (int u = 0; u < 8; u++) acc[v][u] += a[v] * b[u];
        }
        __syncthreads();
    }

    // masked thresholded accumulation with symmetry weighting
    float local = 0.0f;
    bool diagtile = (ti == tj);
    #pragma unroll
    for (int v = 0; v < 8; v++) {
        int gi = i0 + ty * 8 + v;
        int gj0 = j0 + tx * 8;
        unsigned word = g_adj[gi * (NN / 32) + (gj0 >> 5)];
        unsigned sh = (unsigned)(gj0 & 31);
        #pragma unroll
        for (int u = 0; u < 8; u++) {
            int gj = gj0 + u;
            float cv = acc[v][u];
            bool conn = (word >> (sh + u)) & 1u;
            float fac = diagtile ? ((gj > gi) ? 2.0f : ((gj == gi) ? 1.0f : 0.0f))
                                 : 2.0f;
            if (!conn && cv > C_THRESH) local += cv * fac;
        }
    }
    local = warp_red(local);
    if ((tid & 31) == 0) atomicAdd(&g_psum, (double)local);
}

// ------------------------- final reduction ------------------------------
__global__ void k_final(float* out) {
    __shared__ double red[256];
    int tid = threadIdx.x;
    double h = 0.0;
    for (int n = tid; n < NN; n += 256) {
        float d = g_deg[n];
        if (d == 0.0f) d = 1.0f;
        h += (double)g_scores[n] / (double)d;
    }
    red[tid] = h;
    __syncthreads();
    for (int s = 128; s; s >>= 1) {
        if (tid < s) red[tid] += red[tid + s];
        __syncthreads();
    }
    if (tid == 0) {
        double homo = -red[0] / (double)NN;
        double pen = g_psum / ((double)NN * (double)NN);
        out[0] = (float)(homo + pen);
    }
}

// ------------------------- host launch ----------------------------------
extern "C" void kernel_launch(void* const* d_in, const int* in_sizes, int n_in,
                              void* d_out, int out_size) {
    const float* z = nullptr;
    const void* edges = nullptr;
    const void* fk = nullptr;
    const void* fu = nullptr;
    int seen_nf = 0, seen_n = 0;
    for (int t = 0; t < n_in; t++) {
        if (in_sizes[t] == NN * FF) {
            if (seen_nf == 0) z = (const float*)d_in[t];
            seen_nf++;
        } else if (in_sizes[t] == 2 * EE) {
            edges = d_in[t];
        } else if (in_sizes[t] == NN) {
            if (seen_n == 0) fk = d_in[t];
            else if (seen_n == 1) fu = d_in[t];
            seen_n++;
        }
    }
    float* out = (float*)d_out;

    k_zero<<<2048, 1024>>>();
    k_detect<<<1, 32>>>(edges, fk, fu);
    k_convert<<<EE / 256, 256>>>(edges);
    k_wcalc<<<NN / 256, 256>>>(fk, fu);
    k_colsum<<<64, 256>>>(z);
    k_gram<<<dim3(10, 32), 256>>>(z);
    k_cor<<<FF, FF>>>();
    k_z2<<<NN / 32, 256>>>(z);
    k_adj<<<EE / 256, 256>>>();
    k_norms<<<NN / 8, 256>>>();
    k_edge<<<EE / 8, 256>>>();
    k_big<<<64 * 65 / 2, 256>>>();
    k_final<<<1, 256>>>(out);
    (void)out_size;
}

// round 9
// speedup vs baseline: 2.0079x; 2.0079x over previous
#include <cuda_runtime.h>
#include <cuda_bf16.h>
#include <cstdint>
#include <math.h>

static constexpr int NN = 8192;
static constexpr int FF = 256;
static constexpr int EE = 262144;
static constexpr float C_ALPHA  = 0.9f;
static constexpr float C_EPS    = 0.01f;
static constexpr float C_THRESH = 0.8f;
static constexpr float C_COSEPS = 1e-8f;

// ------------------------- device scratch (no runtime alloc allowed) -------
__device__ float          g_mean[FF];
__device__ float          g_G[FF * FF];
__device__ float          g_cor[FF * FF];
__device__ float          g_w[NN];
__device__ float          g_z2[NN * FF];
__device__ __nv_bfloat16  g_zb[NN * FF];        // bf16 copy of z2 (4 MB)
__device__ float          g_inorm[NN];
__device__ float          g_scores[NN];
__device__ float          g_deg[NN];
__device__ unsigned       g_adj[NN * NN / 32];  // 8 MB bitmask
__device__ int            g_ei[EE];
__device__ int            g_ej[EE];
__device__ double         g_psum;
__device__ int            g_flag_e, g_flag_k, g_flag_u;

__device__ __forceinline__ float warp_red(float v) {
    #pragma unroll
    for (int o = 16; o; o >>= 1) v += __shfl_xor_sync(0xffffffffu, v, o);
    return v;
}

__device__ __forceinline__ uint32_t smem_addr_u32(const void* p) {
    uint32_t a;
    asm("{ .reg .u64 t; cvta.to.shared.u64 t, %1; cvt.u32.u64 %0, t; }"
        : "=r"(a) : "l"(p));
    return a;
}

#define LDSM4(r, a)                                                         \
    asm volatile("ldmatrix.sync.aligned.m8n8.x4.shared.b16 "                \
                 "{%0, %1, %2, %3}, [%4];"                                  \
                 : "=r"((r)[0]), "=r"((r)[1]), "=r"((r)[2]), "=r"((r)[3])   \
                 : "r"(a))

#define MMA16816(d, a, b0, b1)                                              \
    asm volatile("mma.sync.aligned.m16n8k16.row.col.f32.bf16.bf16.f32 "     \
                 "{%0, %1, %2, %3}, {%4, %5, %6, %7}, {%8, %9}, "           \
                 "{%0, %1, %2, %3};"                                        \
                 : "+f"((d)[0]), "+f"((d)[1]), "+f"((d)[2]), "+f"((d)[3])   \
                 : "r"((a)[0]), "r"((a)[1]), "r"((a)[2]), "r"((a)[3]),      \
                   "r"(b0), "r"(b1))

// ------------------------- zeroing --------------------------------------
__global__ void k_zero() {
    int idx = blockIdx.x * blockDim.x + threadIdx.x;
    int stride = gridDim.x * blockDim.x;
    for (int i = idx; i < NN * NN / 32; i += stride) g_adj[i] = 0u;
    for (int i = idx; i < FF * FF; i += stride) g_G[i] = 0.0f;
    for (int i = idx; i < NN; i += stride) { g_scores[i] = 0.0f; g_deg[i] = 0.0f; }
    for (int i = idx; i < FF; i += stride) g_mean[i] = 0.0f;
    if (idx == 0) g_psum = 0.0;
}

// ------------------------- dtype detection ------------------------------
__device__ __forceinline__ int detect64(const void* p, long long bound) {
    const long long* q = (const long long*)p;
    int c = 0;
    for (int s = 0; s < 64; s++) {
        long long v = q[s];
        if (v >= 0 && v < bound) c++;
    }
    return c >= 60 ? 1 : 0;
}

__global__ void k_detect(const void* ep, const void* kp, const void* up) {
    if (threadIdx.x == 0) g_flag_e = detect64(ep, NN);
    else if (threadIdx.x == 1) g_flag_k = detect64(kp, 6);
    else if (threadIdx.x == 2) g_flag_u = detect64(up, 32);
}

// convert edges + build adjacency bitmask in one pass
__global__ void k_convert(const void* ep) {
    int e = blockIdx.x * blockDim.x + threadIdx.x;
    if (e >= EE) return;
    int i, j;
    if (g_flag_e) {
        const long long* p = (const long long*)ep;
        i = (int)p[e]; j = (int)p[EE + e];
    } else {
        const int* p = (const int*)ep;
        i = p[e]; j = p[EE + e];
    }
    g_ei[e] = i;
    g_ej[e] = j;
    atomicOr(&g_adj[(i * NN + j) >> 5], 1u << (j & 31));
    atomicOr(&g_adj[(j * NN + i) >> 5], 1u << (i & 31));
}

__global__ void k_wcalc(const void* kp, const void* up) {
    int n = blockIdx.x * blockDim.x + threadIdx.x;
    if (n >= NN) return;
    float fk, fu;
    if (g_flag_k) fk = (float)((const long long*)kp)[n];
    else          fk = (float)((const int*)kp)[n];
    if (g_flag_u) fu = (float)((const long long*)up)[n];
    else          fu = (float)((const int*)up)[n];
    g_w[n] = powf(C_ALPHA, fk) + 1.0f - powf(C_ALPHA, fu);
}

// ------------------------- column sums (means) --------------------------
__global__ void k_colsum(const float* __restrict__ z) {
    int t = threadIdx.x;
    int r0 = blockIdx.x * 128;
    float acc = 0.0f;
    for (int m = 0; m < 128; m++) acc += z[(r0 + m) * FF + t];
    atomicAdd(&g_mean[t], acc);
}

// ------------------------- Gram matrix G = z^T z (split-K) --------------
__global__ void k_gram(const float* __restrict__ z) {
    __shared__ float As[8][64];
    __shared__ float Bs[8][64];
    int p = blockIdx.x, ti = 0;
    while (p >= 4 - ti) { p -= 4 - ti; ti++; }
    int tj = ti + p;
    int i0 = ti * 64, j0 = tj * 64;
    int k0 = blockIdx.y * 256;
    int tid = threadIdx.x;
    int tx = tid & 15, ty = tid >> 4;
    float c[4][4];
    #pragma unroll
    for (int a = 0; a < 4; a++)
        #pragma unroll
        for (int b = 0; b < 4; b++) c[a][b] = 0.0f;

    for (int ks = 0; ks < 256; ks += 8) {
        int f2 = tid * 2;
        int kk = f2 >> 6, cc = f2 & 63;
        As[kk][cc]     = z[(k0 + ks + kk) * FF + i0 + cc];
        As[kk][cc + 1] = z[(k0 + ks + kk) * FF + i0 + cc + 1];
        Bs[kk][cc]     = z[(k0 + ks + kk) * FF + j0 + cc];
        Bs[kk][cc + 1] = z[(k0 + ks + kk) * FF + j0 + cc + 1];
        __syncthreads();
        #pragma unroll
        for (int q = 0; q < 8; q++) {
            float4 av = *(const float4*)&As[q][ty * 4];
            float4 bv = *(const float4*)&Bs[q][tx * 4];
            float aa[4] = {av.x, av.y, av.z, av.w};
            float bb[4] = {bv.x, bv.y, bv.z, bv.w};
            #pragma unroll
            for (int a = 0; a < 4; a++)
                #pragma unroll
                for (int b = 0; b < 4; b++) c[a][b] += aa[a] * bb[b];
        }
        __syncthreads();
    }
    #pragma unroll
    for (int a = 0; a < 4; a++) {
        int gi = i0 + ty * 4 + a;
        #pragma unroll
        for (int b = 0; b < 4; b++) {
            int gj = j0 + tx * 4 + b;
            atomicAdd(&g_G[gi * FF + gj], c[a][b]);
            if (ti != tj) atomicAdd(&g_G[gj * FF + gi], c[a][b]);
        }
    }
}

// ------------------------- correlation matrix ---------------------------
__global__ void k_cor() {
    int i = blockIdx.x, j = threadIdx.x;
    float mi = g_mean[i] / (float)NN;
    float mj = g_mean[j] / (float)NN;
    float cov = g_G[i * FF + j] - (float)NN * mi * mj;
    float vii = g_G[i * FF + i] - (float)NN * mi * mi;
    float vjj = g_G[j * FF + j] - (float)NN * mj * mj;
    float c = cov / (sqrtf(vii) * sqrtf(vjj));
    if (isnan(c)) c = 0.0f;
    c = fminf(fmaxf(c, -1.0f), 1.0f);
    if (i == j) c = 0.0f;
    g_cor[i * FF + j] = c;
}

// ------------------------- z2 = z + eps * w * ((z-mean) @ cor) ----------
__global__ void k_z2(const float* __restrict__ z) {
    __shared__ float xs[32][FF];
    __shared__ float ws[32];
    int tid = threadIdx.x;
    int r0 = blockIdx.x * 32;
    float meanv = g_mean[tid] / (float)NN;
    for (int m = 0; m < 32; m++)
        xs[m][tid] = z[(r0 + m) * FF + tid] - meanv;
    if (tid < 32) ws[tid] = g_w[r0 + tid];
    __syncthreads();

    float acc[32];
    #pragma unroll
    for (int m = 0; m < 32; m++) acc[m] = 0.0f;

    for (int k = 0; k < FF; k += 4) {
        float c0 = g_cor[(k + 0) * FF + tid];
        float c1 = g_cor[(k + 1) * FF + tid];
        float c2 = g_cor[(k + 2) * FF + tid];
        float c3 = g_cor[(k + 3) * FF + tid];
        #pragma unroll
        for (int m = 0; m < 32; m++) {
            float4 xv = *(const float4*)&xs[m][k];
            acc[m] += xv.x * c0 + xv.y * c1 + xv.z * c2 + xv.w * c3;
        }
    }
    #pragma unroll
    for (int m = 0; m < 32; m++) {
        int row = r0 + m;
        g_z2[row * FF + tid] = z[row * FF + tid] + C_EPS * ws[m] * acc[m];
    }
}

// ------------------------- z2 -> bf16 -----------------------------------
__global__ void k_tobf16() {
    int t = blockIdx.x * blockDim.x + threadIdx.x;
    const float4* src = (const float4*)g_z2;
    float4 v0 = src[t * 2];
    float4 v1 = src[t * 2 + 1];
    __nv_bfloat162 b0 = __float22bfloat162_rn(make_float2(v0.x, v0.y));
    __nv_bfloat162 b1 = __float22bfloat162_rn(make_float2(v0.z, v0.w));
    __nv_bfloat162 b2 = __float22bfloat162_rn(make_float2(v1.x, v1.y));
    __nv_bfloat162 b3 = __float22bfloat162_rn(make_float2(v1.z, v1.w));
    uint4 o;
    o.x = *(unsigned*)&b0; o.y = *(unsigned*)&b1;
    o.z = *(unsigned*)&b2; o.w = *(unsigned*)&b3;
    ((uint4*)g_zb)[t] = o;
}

// ------------------------- per-node inverse norms (fp32) ----------------
__global__ void k_norms() {
    int warp = threadIdx.x >> 5, lane = threadIdx.x & 31;
    int row = blockIdx.x * 8 + warp;
    const float* p = &g_z2[row * FF];
    float4 a = *(const float4*)&p[lane * 4];
    float4 b = *(const float4*)&p[128 + lane * 4];
    float s = a.x * a.x + a.y * a.y + a.z * a.z + a.w * a.w
            + b.x * b.x + b.y * b.y + b.z * b.z + b.w * b.w;
    s = warp_red(s);
    if (lane == 0) g_inorm[row] = 1.0f / fmaxf(sqrtf(s), C_COSEPS);
}

// ------------------------- homophily: warp per edge (bf16 rows) ---------
__device__ __forceinline__ float bdot(unsigned ua, unsigned ub) {
    float2 fa = __bfloat1622float2(*(__nv_bfloat162*)&ua);
    float2 fb = __bfloat1622float2(*(__nv_bfloat162*)&ub);
    return fa.x * fb.x + fa.y * fb.y;
}

__global__ void k_edge() {
    int warp = threadIdx.x >> 5, lane = threadIdx.x & 31;
    int e = blockIdx.x * 8 + warp;
    int i = g_ei[e], j = g_ej[e];
    const uint4* pi = (const uint4*)&g_zb[i * FF];
    const uint4* pj = (const uint4*)&g_zb[j * FF];
    uint4 a = pi[lane];
    uint4 b = pj[lane];
    float d = bdot(a.x, b.x) + bdot(a.y, b.y) + bdot(a.z, b.z) + bdot(a.w, b.w);
    d = warp_red(d);
    if (lane == 0) {
        float sim = d * g_inorm[i] * g_inorm[j];
        atomicAdd(&g_scores[i], sim);
        atomicAdd(&g_deg[i], 1.0f);
    }
}

// ------------------------- big masked GEMM via mma.sync (HMMA bf16) -----
// One CTA per upper-triangle tile pair (ti<=tj), 128x128 fp32 accum in regs.
// 8 warps: warp = (wm 0..1) x (wn 0..3); warp tile 64(i) x 32(j), K=256.
// SMEM tiles: 128 rows x 256 bf16 (512B/row), 16B-granule XOR swizzle.
static constexpr int BIG_SMEM = 1024 + 2 * 65536;

__global__ __launch_bounds__(256, 1) void k_big_mma() {
    extern __shared__ char smem[];
    uint32_t raw = smem_addr_u32(smem);
    uint32_t base = (raw + 1023u) & ~1023u;
    char* sb = smem + (base - raw);
    uint32_t A_addr = base;
    uint32_t B_addr = base + 65536;
    char* A_ptr = sb;
    char* B_ptr = sb + 65536;

    int tid = threadIdx.x;
    int wid = tid >> 5, lid = tid & 31;

    int p = blockIdx.x, ti = 0;
    while (p >= 64 - ti) { p -= 64 - ti; ti++; }
    int tj = ti + p;
    int i0 = ti * 128, j0 = tj * 128;
    bool diag = (ti == tj);

    // cooperative swizzled fill: 4096 granules of 16B per tile
    for (int idx = tid; idx < 4096; idx += 256) {
        int r = idx >> 5, g = idx & 31;
        uint32_t sw = (uint32_t)(r * 512 + ((g ^ (r & 7)) << 4));
        *(uint4*)(A_ptr + sw) = *(const uint4*)&g_zb[(i0 + r) * FF + g * 8];
        if (!diag)
            *(uint4*)(B_ptr + sw) = *(const uint4*)&g_zb[(j0 + r) * FF + g * 8];
    }
    __syncthreads();

    int wm = wid >> 2;        // 0..1 : 64-row block
    int wn = wid & 3;         // 0..3 : 32-col block

    // ldmatrix lane address components
    int lrA = wm * 64 + (lid & 15);                       // A row (per mt add 16)
    int lrB = wn * 32 + ((lid >> 4) << 3) + (lid & 7);    // B row (per q add 16)
    int ksA = lid >> 4;                                   // k-granule select
    int ksB = (lid >> 3) & 1;
    uint32_t Abase = A_addr + (uint32_t)(lrA * 512);
    uint32_t Bbase = (diag ? A_addr : B_addr) + (uint32_t)(lrB * 512);
    int rA7 = lrA & 7, rB7 = lrB & 7;

    float acc[4][4][4];
    #pragma unroll
    for (int a = 0; a < 4; a++)
        #pragma unroll
        for (int b = 0; b < 4; b++)
            #pragma unroll
            for (int c = 0; c < 4; c++) acc[a][b][c] = 0.0f;

    #pragma unroll
    for (int ks = 0; ks < 16; ks++) {
        uint32_t af[4][4];
        uint32_t bf[2][4];
        int kgA = ks * 2 + ksA;
        int kgB = ks * 2 + ksB;
        uint32_t offA = (uint32_t)((kgA ^ rA7) << 4);
        uint32_t offB = (uint32_t)((kgB ^ rB7) << 4);
        #pragma unroll
        for (int mt = 0; mt < 4; mt++)
            LDSM4(af[mt], Abase + (uint32_t)(mt * 16 * 512) + offA);
        #pragma unroll
        for (int q = 0; q < 2; q++)
            LDSM4(bf[q], Bbase + (uint32_t)(q * 16 * 512) + offB);
        #pragma unroll
        for (int mt = 0; mt < 4; mt++) {
            MMA16816(acc[mt][0], af[mt], bf[0][0], bf[0][1]);
            MMA16816(acc[mt][1], af[mt], bf[0][2], bf[0][3]);
            MMA16816(acc[mt][2], af[mt], bf[1][0], bf[1][1]);
            MMA16816(acc[mt][3], af[mt], bf[1][2], bf[1][3]);
        }
    }

    // masked thresholded accumulation (symmetry weighting)
    int jcol = (j0 + wn * 32) >> 5;        // warp's 32 j-cols = one adj word
    float local = 0.0f;
    #pragma unroll
    for (int mt = 0; mt < 4; mt++) {
        #pragma unroll
        for (int half = 0; half < 2; half++) {
            int gi = i0 + wm * 64 + mt * 16 + (lid >> 2) + half * 8;
            unsigned word = g_adj[gi * (NN / 32) + jcol];
            #pragma unroll
            for (int nt = 0; nt < 4; nt++) {
                #pragma unroll
                for (int e = 0; e < 2; e++) {
                    int gj = j0 + wn * 32 + nt * 8 + 2 * (lid & 3) + e;
                    float cv = acc[mt][nt][half * 2 + e];
                    bool conn = (word >> (gj & 31)) & 1u;
                    float fac = diag ? ((gj > gi) ? 2.0f : ((gj == gi) ? 1.0f : 0.0f))
                                     : 2.0f;
                    if (!conn && cv > C_THRESH) local += cv * fac;
                }
            }
        }
    }
    local = warp_red(local);
    if (lid == 0) atomicAdd(&g_psum, (double)local);
}

// ------------------------- final reduction ------------------------------
__global__ void k_final(float* out) {
    __shared__ double red[256];
    int tid = threadIdx.x;
    double h = 0.0;
    for (int n = tid; n < NN; n += 256) {
        float d = g_deg[n];
        if (d == 0.0f) d = 1.0f;
        h += (double)g_scores[n] / (double)d;
    }
    red[tid] = h;
    __syncthreads();
    for (int s = 128; s; s >>= 1) {
        if (tid < s) red[tid] += red[tid + s];
        __syncthreads();
    }
    if (tid == 0) {
        double homo = -red[0] / (double)NN;
        double pen = g_psum / ((double)NN * (double)NN);
        out[0] = (float)(homo + pen);
    }
}

// ------------------------- host launch ----------------------------------
extern "C" void kernel_launch(void* const* d_in, const int* in_sizes, int n_in,
                              void* d_out, int out_size) {
    const float* z = nullptr;
    const void* edges = nullptr;
    const void* fk = nullptr;
    const void* fu = nullptr;
    int seen_nf = 0, seen_n = 0;
    for (int t = 0; t < n_in; t++) {
        if (in_sizes[t] == NN * FF) {
            if (seen_nf == 0) z = (const float*)d_in[t];
            seen_nf++;
        } else if (in_sizes[t] == 2 * EE) {
            edges = d_in[t];
        } else if (in_sizes[t] == NN) {
            if (seen_n == 0) fk = d_in[t];
            else if (seen_n == 1) fu = d_in[t];
            seen_n++;
        }
    }
    float* out = (float*)d_out;

    cudaFuncSetAttribute(k_big_mma, cudaFuncAttributeMaxDynamicSharedMemorySize, BIG_SMEM);

    k_zero<<<2048, 1024>>>();
    k_detect<<<1, 32>>>(edges, fk, fu);
    k_convert<<<EE / 256, 256>>>(edges);
    k_wcalc<<<NN / 256, 256>>>(fk, fu);
    k_colsum<<<64, 256>>>(z);
    k_gram<<<dim3(10, 32), 256>>>(z);
    k_cor<<<FF, FF>>>();
    k_z2<<<NN / 32, 256>>>(z);
    k_tobf16<<<1024, 256>>>();
    k_norms<<<NN / 8, 256>>>();
    k_edge<<<EE / 8, 256>>>();
    k_big_mma<<<64 * 65 / 2, 256, BIG_SMEM>>>();
    k_final<<<1, 256>>>(out);
    (void)out_size;
}

// round 11
// speedup vs baseline: 2.9086x; 1.4486x over previous
#include <cuda_runtime.h>
#include <cuda_bf16.h>
#include <cstdint>
#include <math.h>

static constexpr int NN = 8192;
static constexpr int FF = 256;
static constexpr int EE = 262144;
static constexpr float C_ALPHA  = 0.9f;
static constexpr float C_EPS    = 0.01f;
static constexpr float C_THRESH = 0.8f;
static constexpr float C_COSEPS = 1e-8f;

// ------------------------- device scratch (no runtime alloc allowed) -------
__device__ float          g_mean[FF];
__device__ float          g_G[FF * FF];
__device__ float          g_cor[FF * FF];
__device__ __nv_bfloat16  g_corb[FF * FF];
__device__ float          g_w[NN];
__device__ __nv_bfloat16  g_wb[NN * FF];       // bf16 of w*(z-mean) (4 MB)
__device__ __nv_bfloat16  g_zt[FF * NN];       // bf16 of z^T (4 MB)
__device__ __nv_bfloat16  g_zb[NN * FF];       // bf16 of z2 (4 MB)
__device__ float          g_inorm[NN];
__device__ float          g_scores[NN];
__device__ float          g_deg[NN];
__device__ unsigned       g_adj[NN * NN / 32]; // 8 MB bitmask
__device__ int            g_ei[EE];
__device__ int            g_ej[EE];
__device__ double         g_psum;
__device__ int            g_flag_e, g_flag_k, g_flag_u;

__device__ __forceinline__ float warp_red(float v) {
    #pragma unroll
    for (int o = 16; o; o >>= 1) v += __shfl_xor_sync(0xffffffffu, v, o);
    return v;
}

__device__ __forceinline__ uint32_t smem_addr_u32(const void* p) {
    uint32_t a;
    asm("{ .reg .u64 t; cvta.to.shared.u64 t, %1; cvt.u32.u64 %0, t; }"
        : "=r"(a) : "l"(p));
    return a;
}

#define LDSM4(r, a)                                                         \
    asm volatile("ldmatrix.sync.aligned.m8n8.x4.shared.b16 "                \
                 "{%0, %1, %2, %3}, [%4];"                                  \
                 : "=r"((r)[0]), "=r"((r)[1]), "=r"((r)[2]), "=r"((r)[3])   \
                 : "r"(a))

#define MMA16816(d, a, b0, b1)                                              \
    asm volatile("mma.sync.aligned.m16n8k16.row.col.f32.bf16.bf16.f32 "     \
                 "{%0, %1, %2, %3}, {%4, %5, %6, %7}, {%8, %9}, "           \
                 "{%0, %1, %2, %3};"                                        \
                 : "+f"((d)[0]), "+f"((d)[1]), "+f"((d)[2]), "+f"((d)[3])   \
                 : "r"((a)[0]), "r"((a)[1]), "r"((a)[2]), "r"((a)[3]),      \
                   "r"(b0), "r"(b1))

// ------------------------- zeroing --------------------------------------
__global__ void k_zero() {
    int idx = blockIdx.x * blockDim.x + threadIdx.x;
    int stride = gridDim.x * blockDim.x;
    for (int i = idx; i < NN * NN / 32; i += stride) g_adj[i] = 0u;
    for (int i = idx; i < FF * FF; i += stride) g_G[i] = 0.0f;
    for (int i = idx; i < NN; i += stride) { g_scores[i] = 0.0f; g_deg[i] = 0.0f; }
    for (int i = idx; i < FF; i += stride) g_mean[i] = 0.0f;
    if (idx == 0) g_psum = 0.0;
}

// ------------------------- dtype detection ------------------------------
__device__ __forceinline__ int detect64(const void* p, long long bound) {
    const long long* q = (const long long*)p;
    int c = 0;
    for (int s = 0; s < 64; s++) {
        long long v = q[s];
        if (v >= 0 && v < bound) c++;
    }
    return c >= 60 ? 1 : 0;
}

__global__ void k_detect(const void* ep, const void* kp, const void* up) {
    if (threadIdx.x == 0) g_flag_e = detect64(ep, NN);
    else if (threadIdx.x == 1) g_flag_k = detect64(kp, 6);
    else if (threadIdx.x == 2) g_flag_u = detect64(up, 32);
}

// convert edges + build adjacency bitmask in one pass
__global__ void k_convert(const void* ep) {
    int e = blockIdx.x * blockDim.x + threadIdx.x;
    if (e >= EE) return;
    int i, j;
    if (g_flag_e) {
        const long long* p = (const long long*)ep;
        i = (int)p[e]; j = (int)p[EE + e];
    } else {
        const int* p = (const int*)ep;
        i = p[e]; j = p[EE + e];
    }
    g_ei[e] = i;
    g_ej[e] = j;
    atomicOr(&g_adj[(i * NN + j) >> 5], 1u << (j & 31));
    atomicOr(&g_adj[(j * NN + i) >> 5], 1u << (i & 31));
}

__global__ void k_wcalc(const void* kp, const void* up) {
    int n = blockIdx.x * blockDim.x + threadIdx.x;
    if (n >= NN) return;
    float fk, fu;
    if (g_flag_k) fk = (float)((const long long*)kp)[n];
    else          fk = (float)((const int*)kp)[n];
    if (g_flag_u) fu = (float)((const long long*)up)[n];
    else          fu = (float)((const int*)up)[n];
    g_w[n] = powf(C_ALPHA, fk) + 1.0f - powf(C_ALPHA, fu);
}

// ------------------------- column sums (means) --------------------------
__global__ void k_colsum(const float* __restrict__ z) {
    int t = threadIdx.x;
    int r0 = blockIdx.x * 128;
    float acc = 0.0f;
    for (int m = 0; m < 128; m++) acc += z[(r0 + m) * FF + t];
    atomicAdd(&g_mean[t], acc);
}

// ------------------------- transpose z -> g_zt (bf16, [F][N]) -----------
__global__ void k_trans(const float* __restrict__ z) {
    __shared__ __nv_bfloat16 s[64][66];
    int n0 = blockIdx.x * 64, f0 = blockIdx.y * 64;
    int tid = threadIdx.x;
    int c = tid & 63, r4 = tid >> 6;
    #pragma unroll
    for (int i = 0; i < 16; i++) {
        int r = r4 + i * 4;
        s[c][r] = __float2bfloat16(z[(n0 + r) * FF + f0 + c]);
    }
    __syncthreads();
    #pragma unroll
    for (int i = 0; i < 16; i++) {
        int cc = r4 + i * 4;
        g_zt[(f0 + cc) * NN + n0 + (tid & 63)] = s[cc][tid & 63];
    }
}

// ------------------------- Gram G = z^T z via HMMA ----------------------
// 3 feature-tile pairs (128x128) x 32 K-slices of 256 nodes. atomic fp32 out.
static constexpr int GEMM_SMEM = 1024 + 2 * 65536;

__global__ __launch_bounds__(256, 1) void k_gram_mma() {
    extern __shared__ char smem[];
    uint32_t raw = smem_addr_u32(smem);
    uint32_t base = (raw + 1023u) & ~1023u;
    char* sb = smem + (base - raw);
    uint32_t A_addr = base;
    uint32_t B_addr = base + 65536;
    char* A_ptr = sb;
    char* B_ptr = sb + 65536;

    int tid = threadIdx.x;
    int wid = tid >> 5, lid = tid & 31;

    int p = blockIdx.x % 3;
    int k0 = (blockIdx.x / 3) * 256;
    int ti = (p == 2) ? 1 : 0;
    int tj = (p == 0) ? 0 : 1;
    bool diag = (ti == tj);

    for (int idx = tid; idx < 4096; idx += 256) {
        int r = idx >> 5, g = idx & 31;
        uint32_t sw = (uint32_t)(r * 512 + ((g ^ (r & 7)) << 4));
        *(uint4*)(A_ptr + sw) = *(const uint4*)&g_zt[(ti * 128 + r) * NN + k0 + g * 8];
        if (!diag)
            *(uint4*)(B_ptr + sw) = *(const uint4*)&g_zt[(tj * 128 + r) * NN + k0 + g * 8];
    }
    __syncthreads();

    int wm = wid >> 2, wn = wid & 3;
    int lrA = wm * 64 + (lid & 15);
    int lrB = wn * 32 + ((lid >> 4) << 3) + (lid & 7);
    int ksA = lid >> 4, ksB = (lid >> 3) & 1;
    uint32_t Abase = A_addr + (uint32_t)(lrA * 512);
    uint32_t Bbase = (diag ? A_addr : B_addr) + (uint32_t)(lrB * 512);
    int rA7 = lrA & 7, rB7 = lrB & 7;

    float acc[4][4][4];
    #pragma unroll
    for (int a = 0; a < 4; a++)
        #pragma unroll
        for (int b = 0; b < 4; b++)
            #pragma unroll
            for (int cc = 0; cc < 4; cc++) acc[a][b][cc] = 0.0f;

    #pragma unroll
    for (int ks = 0; ks < 16; ks++) {
        uint32_t af[4][4], bf[2][4];
        uint32_t offA = (uint32_t)(((ks * 2 + ksA) ^ rA7) << 4);
        uint32_t offB = (uint32_t)(((ks * 2 + ksB) ^ rB7) << 4);
        #pragma unroll
        for (int mt = 0; mt < 4; mt++)
            LDSM4(af[mt], Abase + (uint32_t)(mt * 16 * 512) + offA);
        #pragma unroll
        for (int q = 0; q < 2; q++)
            LDSM4(bf[q], Bbase + (uint32_t)(q * 16 * 512) + offB);
        #pragma unroll
        for (int mt = 0; mt < 4; mt++) {
            MMA16816(acc[mt][0], af[mt], bf[0][0], bf[0][1]);
            MMA16816(acc[mt][1], af[mt], bf[0][2], bf[0][3]);
            MMA16816(acc[mt][2], af[mt], bf[1][0], bf[1][1]);
            MMA16816(acc[mt][3], af[mt], bf[1][2], bf[1][3]);
        }
    }

    #pragma unroll
    for (int mt = 0; mt < 4; mt++)
        #pragma unroll
        for (int half = 0; half < 2; half++) {
            int gi = ti * 128 + wm * 64 + mt * 16 + (lid >> 2) + half * 8;
            #pragma unroll
            for (int nt = 0; nt < 4; nt++)
                #pragma unroll
                for (int e = 0; e < 2; e++) {
                    int gj = tj * 128 + wn * 32 + nt * 8 + 2 * (lid & 3) + e;
                    float cv = acc[mt][nt][half * 2 + e];
                    atomicAdd(&g_G[gi * FF + gj], cv);
                    if (!diag) atomicAdd(&g_G[gj * FF + gi], cv);
                }
        }
}

// ------------------------- correlation matrix (fp32 + bf16 copy) --------
__global__ void k_cor() {
    int i = blockIdx.x, j = threadIdx.x;
    float mi = g_mean[i] / (float)NN;
    float mj = g_mean[j] / (float)NN;
    float cov = g_G[i * FF + j] - (float)NN * mi * mj;
    float vii = g_G[i * FF + i] - (float)NN * mi * mi;
    float vjj = g_G[j * FF + j] - (float)NN * mj * mj;
    float c = cov / (sqrtf(vii) * sqrtf(vjj));
    if (isnan(c)) c = 0.0f;
    c = fminf(fmaxf(c, -1.0f), 1.0f);
    if (i == j) c = 0.0f;
    g_cor[i * FF + j] = c;
    g_corb[i * FF + j] = __float2bfloat16(c);
}

// ------------------------- W = w * (z - mean) in bf16 -------------------
__global__ void k_wb(const float* __restrict__ z) {
    int t = blockIdx.x * blockDim.x + threadIdx.x;
    for (int idx = t; idx < NN * FF; idx += gridDim.x * blockDim.x) {
        int row = idx >> 8, col = idx & 255;
        float v = g_w[row] * (z[idx] - g_mean[col] / (float)NN);
        g_wb[idx] = __float2bfloat16(v);
    }
}

// ------------------------- z2 via HMMA: z + eps * (W @ cor) -> g_zb -----
__global__ __launch_bounds__(256, 1) void k_z2_mma(const float* __restrict__ z) {
    extern __shared__ char smem[];
    uint32_t raw = smem_addr_u32(smem);
    uint32_t base = (raw + 1023u) & ~1023u;
    char* sb = smem + (base - raw);
    uint32_t A_addr = base;
    uint32_t B_addr = base + 65536;
    char* A_ptr = sb;
    char* B_ptr = sb + 65536;

    int tid = threadIdx.x;
    int wid = tid >> 5, lid = tid & 31;

    int i0 = (blockIdx.x >> 1) * 128;     // node tile
    int j0 = (blockIdx.x & 1) * 128;      // output-feature tile

    for (int idx = tid; idx < 4096; idx += 256) {
        int r = idx >> 5, g = idx & 31;
        uint32_t sw = (uint32_t)(r * 512 + ((g ^ (r & 7)) << 4));
        *(uint4*)(A_ptr + sw) = *(const uint4*)&g_wb[(i0 + r) * FF + g * 8];
        *(uint4*)(B_ptr + sw) = *(const uint4*)&g_corb[(j0 + r) * FF + g * 8];
    }
    __syncthreads();

    int wm = wid >> 2, wn = wid & 3;
    int lrA = wm * 64 + (lid & 15);
    int lrB = wn * 32 + ((lid >> 4) << 3) + (lid & 7);
    int ksA = lid >> 4, ksB = (lid >> 3) & 1;
    uint32_t Abase = A_addr + (uint32_t)(lrA * 512);
    uint32_t Bbase = B_addr + (uint32_t)(lrB * 512);
    int rA7 = lrA & 7, rB7 = lrB & 7;

    float acc[4][4][4];
    #pragma unroll
    for (int a = 0; a < 4; a++)
        #pragma unroll
        for (int b = 0; b < 4; b++)
            #pragma unroll
            for (int cc = 0; cc < 4; cc++) acc[a][b][cc] = 0.0f;

    #pragma unroll
    for (int ks = 0; ks < 16; ks++) {
        uint32_t af[4][4], bf[2][4];
        uint32_t offA = (uint32_t)(((ks * 2 + ksA) ^ rA7) << 4);
        uint32_t offB = (uint32_t)(((ks * 2 + ksB) ^ rB7) << 4);
        #pragma unroll
        for (int mt = 0; mt < 4; mt++)
            LDSM4(af[mt], Abase + (uint32_t)(mt * 16 * 512) + offA);
        #pragma unroll
        for (int q = 0; q < 2; q++)
            LDSM4(bf[q], Bbase + (uint32_t)(q * 16 * 512) + offB);
        #pragma unroll
        for (int mt = 0; mt < 4; mt++) {
            MMA16816(acc[mt][0], af[mt], bf[0][0], bf[0][1]);
            MMA16816(acc[mt][1], af[mt], bf[0][2], bf[0][3]);
            MMA16816(acc[mt][2], af[mt], bf[1][0], bf[1][1]);
            MMA16816(acc[mt][3], af[mt], bf[1][2], bf[1][3]);
        }
    }

    #pragma unroll
    for (int mt = 0; mt < 4; mt++)
        #pragma unroll
        for (int half = 0; half < 2; half++) {
            int gi = i0 + wm * 64 + mt * 16 + (lid >> 2) + half * 8;
            #pragma unroll
            for (int nt = 0; nt < 4; nt++)
                #pragma unroll
                for (int e = 0; e < 2; e++) {
                    int gj = j0 + wn * 32 + nt * 8 + 2 * (lid & 3) + e;
                    int idx = gi * FF + gj;
                    float v = z[idx] + C_EPS * acc[mt][nt][half * 2 + e];
                    g_zb[idx] = __float2bfloat16(v);
                }
        }
}

// ------------------------- per-node inverse norms (from bf16 z2) --------
__global__ void k_norms() {
    int warp = threadIdx.x >> 5, lane = threadIdx.x & 31;
    int row = blockIdx.x * 8 + warp;
    uint4 a = ((const uint4*)&g_zb[row * FF])[lane];
    float s = 0.0f;
    {
        float2 f;
        f = __bfloat1622float2(*(__nv_bfloat162*)&a.x); s += f.x * f.x + f.y * f.y;
        f = __bfloat1622float2(*(__nv_bfloat162*)&a.y); s += f.x * f.x + f.y * f.y;
        f = __bfloat1622float2(*(__nv_bfloat162*)&a.z); s += f.x * f.x + f.y * f.y;
        f = __bfloat1622float2(*(__nv_bfloat162*)&a.w); s += f.x * f.x + f.y * f.y;
    }
    s = warp_red(s);
    if (lane == 0) g_inorm[row] = 1.0f / fmaxf(sqrtf(s), C_COSEPS);
}

// ------------------------- homophily: warp per edge (bf16 rows) ---------
__device__ __forceinline__ float bdot(unsigned ua, unsigned ub) {
    float2 fa = __bfloat1622float2(*(__nv_bfloat162*)&ua);
    float2 fb = __bfloat1622float2(*(__nv_bfloat162*)&ub);
    return fa.x * fb.x + fa.y * fb.y;
}

__global__ void k_edge() {
    int warp = threadIdx.x >> 5, lane = threadIdx.x & 31;
    int e = blockIdx.x * 8 + warp;
    int i = g_ei[e], j = g_ej[e];
    const uint4* pi = (const uint4*)&g_zb[i * FF];
    const uint4* pj = (const uint4*)&g_zb[j * FF];
    uint4 a = pi[lane];
    uint4 b = pj[lane];
    float d = bdot(a.x, b.x) + bdot(a.y, b.y) + bdot(a.z, b.z) + bdot(a.w, b.w);
    d = warp_red(d);
    if (lane == 0) {
        float sim = d * g_inorm[i] * g_inorm[j];
        atomicAdd(&g_scores[i], sim);
        atomicAdd(&g_deg[i], 1.0f);
    }
}

// ------------------------- big masked GEMM via HMMA (occ 2, K-chunked) --
static constexpr int BIG_SMEM = 1024 + 2 * 32768;

__global__ __launch_bounds__(256, 2) void k_big_mma() {
    extern __shared__ char smem[];
    uint32_t raw = smem_addr_u32(smem);
    uint32_t base = (raw + 1023u) & ~1023u;
    char* sb = smem + (base - raw);
    uint32_t A_addr = base;
    uint32_t B_addr = base + 32768;
    char* A_ptr = sb;
    char* B_ptr = sb + 32768;

    int tid = threadIdx.x;
    int wid = tid >> 5, lid = tid & 31;

    int p = blockIdx.x, ti = 0;
    while (p >= 64 - ti) { p -= 64 - ti; ti++; }
    int tj = ti + p;
    int i0 = ti * 128, j0 = tj * 128;
    bool diag = (ti == tj);

    int wm = wid >> 2, wn = wid & 3;
    int lrA = wm * 64 + (lid & 15);
    int lrB = wn * 32 + ((lid >> 4) << 3) + (lid & 7);
    int ksA = lid >> 4, ksB = (lid >> 3) & 1;
    uint32_t Abase = A_addr + (uint32_t)(lrA * 256);
    uint32_t Bbase = (diag ? A_addr : B_addr) + (uint32_t)(lrB * 256);
    int rA7 = lrA & 7, rB7 = lrB & 7;

    float acc[4][4][4];
    #pragma unroll
    for (int a = 0; a < 4; a++)
        #pragma unroll
        for (int b = 0; b < 4; b++)
            #pragma unroll
            for (int cc = 0; cc < 4; cc++) acc[a][b][cc] = 0.0f;

    for (int ch = 0; ch < 2; ch++) {
        // fill 128-row x 128-col bf16 chunk (16 granules of 16B per row)
        for (int idx = tid; idx < 2048; idx += 256) {
            int r = idx >> 4, g = idx & 15;
            uint32_t sw = (uint32_t)(r * 256 + ((g ^ (r & 7)) << 4));
            *(uint4*)(A_ptr + sw) = *(const uint4*)&g_zb[(i0 + r) * FF + ch * 128 + g * 8];
            if (!diag)
                *(uint4*)(B_ptr + sw) = *(const uint4*)&g_zb[(j0 + r) * FF + ch * 128 + g * 8];
        }
        __syncthreads();

        #pragma unroll
        for (int ks = 0; ks < 8; ks++) {
            uint32_t af[4][4], bf[2][4];
            uint32_t offA = (uint32_t)(((ks * 2 + ksA) ^ rA7) << 4);
            uint32_t offB = (uint32_t)(((ks * 2 + ksB) ^ rB7) << 4);
            #pragma unroll
            for (int mt = 0; mt < 4; mt++)
                LDSM4(af[mt], Abase + (uint32_t)(mt * 16 * 256) + offA);
            #pragma unroll
            for (int q = 0; q < 2; q++)
                LDSM4(bf[q], Bbase + (uint32_t)(q * 16 * 256) + offB);
            #pragma unroll
            for (int mt = 0; mt < 4; mt++) {
                MMA16816(acc[mt][0], af[mt], bf[0][0], bf[0][1]);
                MMA16816(acc[mt][1], af[mt], bf[0][2], bf[0][3]);
                MMA16816(acc[mt][2], af[mt], bf[1][0], bf[1][1]);
                MMA16816(acc[mt][3], af[mt], bf[1][2], bf[1][3]);
            }
        }
        __syncthreads();
    }

    // masked thresholded accumulation (symmetry weighting)
    int jcol = (j0 + wn * 32) >> 5;
    float local = 0.0f;
    #pragma unroll
    for (int mt = 0; mt < 4; mt++)
        #pragma unroll
        for (int half = 0; half < 2; half++) {
            int gi = i0 + wm * 64 + mt * 16 + (lid >> 2) + half * 8;
            unsigned word = g_adj[gi * (NN / 32) + jcol];
            #pragma unroll
            for (int nt = 0; nt < 4; nt++)
                #pragma unroll
                for (int e = 0; e < 2; e++) {
                    int gj = j0 + wn * 32 + nt * 8 + 2 * (lid & 3) + e;
                    float cv = acc[mt][nt][half * 2 + e];
                    bool conn = (word >> (gj & 31)) & 1u;
                    float fac = diag ? ((gj > gi) ? 2.0f : ((gj == gi) ? 1.0f : 0.0f))
                                     : 2.0f;
                    if (!conn && cv > C_THRESH) local += cv * fac;
                }
        }
    local = warp_red(local);
    if (lid == 0) atomicAdd(&g_psum, (double)local);
}

// ------------------------- final reduction ------------------------------
__global__ void k_final(float* out) {
    __shared__ double red[256];
    int tid = threadIdx.x;
    double h = 0.0;
    for (int n = tid; n < NN; n += 256) {
        float d = g_deg[n];
        if (d == 0.0f) d = 1.0f;
        h += (double)g_scores[n] / (double)d;
    }
    red[tid] = h;
    __syncthreads();
    for (int s = 128; s; s >>= 1) {
        if (tid < s) red[tid] += red[tid + s];
        __syncthreads();
    }
    if (tid == 0) {
        double homo = -red[0] / (double)NN;
        double pen = g_psum / ((double)NN * (double)NN);
        out[0] = (float)(homo + pen);
    }
}

// ------------------------- host launch ----------------------------------
extern "C" void kernel_launch(void* const* d_in, const int* in_sizes, int n_in,
                              void* d_out, int out_size) {
    const float* z = nullptr;
    const void* edges = nullptr;
    const void* fk = nullptr;
    const void* fu = nullptr;
    int seen_nf = 0, seen_n = 0;
    for (int t = 0; t < n_in; t++) {
        if (in_sizes[t] == NN * FF) {
            if (seen_nf == 0) z = (const float*)d_in[t];
            seen_nf++;
        } else if (in_sizes[t] == 2 * EE) {
            edges = d_in[t];
        } else if (in_sizes[t] == NN) {
            if (seen_n == 0) fk = d_in[t];
            else if (seen_n == 1) fu = d_in[t];
            seen_n++;
        }
    }
    float* out = (float*)d_out;

    cudaFuncSetAttribute(k_gram_mma, cudaFuncAttributeMaxDynamicSharedMemorySize, GEMM_SMEM);
    cudaFuncSetAttribute(k_z2_mma,   cudaFuncAttributeMaxDynamicSharedMemorySize, GEMM_SMEM);
    cudaFuncSetAttribute(k_big_mma,  cudaFuncAttributeMaxDynamicSharedMemorySize, BIG_SMEM);

    k_zero<<<2048, 1024>>>();
    k_detect<<<1, 32>>>(edges, fk, fu);
    k_convert<<<EE / 256, 256>>>(edges);
    k_wcalc<<<NN / 256, 256>>>(fk, fu);
    k_colsum<<<64, 256>>>(z);
    k_trans<<<dim3(NN / 64, FF / 64), 256>>>(z);
    k_gram_mma<<<96, 256, GEMM_SMEM>>>();
    k_cor<<<FF, FF>>>();
    k_wb<<<1024, 256>>>(z);
    k_z2_mma<<<128, 256, GEMM_SMEM>>>(z);
    k_norms<<<NN / 8, 256>>>();
    k_edge<<<EE / 8, 256>>>();
    k_big_mma<<<64 * 65 / 2, 256, BIG_SMEM>>>();
    k_final<<<1, 256>>>(out);
    (void)out_size;
}

// round 12
// speedup vs baseline: 3.1341x; 1.0775x over previous
#include <cuda_runtime.h>
#include <cuda_bf16.h>
#include <cstdint>
#include <math.h>

static constexpr int NN = 8192;
static constexpr int FF = 256;
static constexpr int EE = 262144;
static constexpr float C_EPS    = 0.01f;
static constexpr float C_THRESH = 0.8f;
static constexpr float C_COSEPS = 1e-8f;
static constexpr float C_L2A    = -0.15200309344504995f;  // log2(0.9)

// ------------------------- device scratch (no runtime alloc allowed) -------
__device__ float          g_mean[FF];
__device__ float          g_G[FF * FF];
__device__ float          g_cor[FF * FF];
__device__ __nv_bfloat16  g_corb[FF * FF];
__device__ float          g_w[NN];
__device__ __nv_bfloat16  g_wb[NN * FF];       // bf16 of w*(z-mean)
__device__ __nv_bfloat16  g_zt[FF * NN];       // bf16 of z^T
__device__ __nv_bfloat16  g_zb[NN * FF];       // bf16 of z2
__device__ float          g_inorm[NN];
__device__ float          g_scores[NN];
__device__ float          g_deg[NN];
__device__ unsigned       g_adj[NN * NN / 32]; // 8 MB bitmask
__device__ int            g_ei[EE];
__device__ int            g_ej[EE];
__device__ double         g_psum;
__device__ int            g_flag_e, g_flag_k, g_flag_u;

__device__ __forceinline__ float warp_red(float v) {
    #pragma unroll
    for (int o = 16; o; o >>= 1) v += __shfl_xor_sync(0xffffffffu, v, o);
    return v;
}

__device__ __forceinline__ uint32_t smem_addr_u32(const void* p) {
    uint32_t a;
    asm("{ .reg .u64 t; cvta.to.shared.u64 t, %1; cvt.u32.u64 %0, t; }"
        : "=r"(a) : "l"(p));
    return a;
}

#define LDSM4(r, a)                                                         \
    asm volatile("ldmatrix.sync.aligned.m8n8.x4.shared.b16 "                \
                 "{%0, %1, %2, %3}, [%4];"                                  \
                 : "=r"((r)[0]), "=r"((r)[1]), "=r"((r)[2]), "=r"((r)[3])   \
                 : "r"(a))

#define MMA16816(d, a, b0, b1)                                              \
    asm volatile("mma.sync.aligned.m16n8k16.row.col.f32.bf16.bf16.f32 "     \
                 "{%0, %1, %2, %3}, {%4, %5, %6, %7}, {%8, %9}, "           \
                 "{%0, %1, %2, %3};"                                        \
                 : "+f"((d)[0]), "+f"((d)[1]), "+f"((d)[2]), "+f"((d)[3])   \
                 : "r"((a)[0]), "r"((a)[1]), "r"((a)[2]), "r"((a)[3]),      \
                   "r"(b0), "r"(b1))

#define CP_ASYNC16(dst, src)                                                \
    asm volatile("cp.async.cg.shared.global [%0], [%1], 16;"                \
                 :: "r"(dst), "l"(__cvta_generic_to_global(src)) : "memory")

#define CP_COMMIT()  asm volatile("cp.async.commit_group;" ::: "memory")
#define CP_WAIT(n)   asm volatile("cp.async.wait_group %0;" :: "n"(n) : "memory")

// ------------------------- dtype detection ------------------------------
__device__ __forceinline__ int detect64(const void* p, long long bound) {
    const long long* q = (const long long*)p;
    int c = 0;
    for (int s = 0; s < 64; s++) {
        long long v = q[s];
        if (v >= 0 && v < bound) c++;
    }
    return c >= 60 ? 1 : 0;
}

// ------------------------- zero + detect --------------------------------
__global__ void k_zero(const void* ep, const void* kp, const void* up) {
    int idx = blockIdx.x * blockDim.x + threadIdx.x;
    int stride = gridDim.x * blockDim.x;
    for (int i = idx; i < NN * NN / 32; i += stride) g_adj[i] = 0u;
    for (int i = idx; i < FF * FF; i += stride) g_G[i] = 0.0f;
    for (int i = idx; i < NN; i += stride) { g_scores[i] = 0.0f; g_deg[i] = 0.0f; }
    for (int i = idx; i < FF; i += stride) g_mean[i] = 0.0f;
    if (idx == 0) {
        g_psum = 0.0;
        g_flag_e = detect64(ep, NN);
        g_flag_k = detect64(kp, 6);
        g_flag_u = detect64(up, 32);
    }
}

// --------------- edges + adjacency + degree + node weights --------------
__global__ void k_convert(const void* ep, const void* kp, const void* up) {
    int e = blockIdx.x * blockDim.x + threadIdx.x;
    if (e >= EE) return;
    int i, j;
    if (g_flag_e) {
        const long long* p = (const long long*)ep;
        i = (int)p[e]; j = (int)p[EE + e];
    } else {
        const int* p = (const int*)ep;
        i = p[e]; j = p[EE + e];
    }
    g_ei[e] = i;
    g_ej[e] = j;
    atomicOr(&g_adj[(i * NN + j) >> 5], 1u << (j & 31));
    atomicOr(&g_adj[(j * NN + i) >> 5], 1u << (i & 31));
    atomicAdd(&g_deg[i], 1.0f);

    if (e < NN) {
        float fk, fu;
        if (g_flag_k) fk = (float)((const long long*)kp)[e];
        else          fk = (float)((const int*)kp)[e];
        if (g_flag_u) fu = (float)((const long long*)up)[e];
        else          fu = (float)((const int*)up)[e];
        g_w[e] = exp2f(fk * C_L2A) + 1.0f - exp2f(fu * C_L2A);
    }
}

// --------------- transpose z -> g_zt (bf16) + column sums ---------------
__global__ void k_trans(const float* __restrict__ z) {
    __shared__ __nv_bfloat16 s[64][66];
    __shared__ float cs[64];
    int n0 = blockIdx.x * 64, f0 = blockIdx.y * 64;
    int tid = threadIdx.x;
    int c = tid & 63, r4 = tid >> 6;
    if (tid < 64) cs[tid] = 0.0f;
    __syncthreads();
    float acc = 0.0f;
    #pragma unroll
    for (int i = 0; i < 16; i++) {
        int r = r4 + i * 4;
        float v = z[(n0 + r) * FF + f0 + c];
        s[c][r] = __float2bfloat16(v);
        acc += v;
    }
    atomicAdd(&cs[c], acc);
    __syncthreads();
    #pragma unroll
    for (int i = 0; i < 16; i++) {
        int cc = r4 + i * 4;
        g_zt[(f0 + cc) * NN + n0 + c] = s[cc][c];
    }
    if (tid < 64) atomicAdd(&g_mean[f0 + tid], cs[tid]);
}

// ------------------------- Gram G = z^T z via HMMA (upper only) ---------
static constexpr int GEMM_SMEM = 1024 + 2 * 65536;

__global__ __launch_bounds__(256, 1) void k_gram_mma() {
    extern __shared__ char smem[];
    uint32_t raw = smem_addr_u32(smem);
    uint32_t base = (raw + 1023u) & ~1023u;
    char* sb = smem + (base - raw);
    uint32_t A_addr = base;
    uint32_t B_addr = base + 65536;
    char* A_ptr = sb;
    char* B_ptr = sb + 65536;

    int tid = threadIdx.x;
    int wid = tid >> 5, lid = tid & 31;

    int p = blockIdx.x % 3;
    int k0 = (blockIdx.x / 3) * 256;
    int ti = (p == 2) ? 1 : 0;
    int tj = (p == 0) ? 0 : 1;
    bool diag = (ti == tj);

    for (int idx = tid; idx < 4096; idx += 256) {
        int r = idx >> 5, g = idx & 31;
        uint32_t sw = (uint32_t)(r * 512 + ((g ^ (r & 7)) << 4));
        *(uint4*)(A_ptr + sw) = *(const uint4*)&g_zt[(ti * 128 + r) * NN + k0 + g * 8];
        if (!diag)
            *(uint4*)(B_ptr + sw) = *(const uint4*)&g_zt[(tj * 128 + r) * NN + k0 + g * 8];
    }
    __syncthreads();

    int wm = wid >> 2, wn = wid & 3;
    int lrA = wm * 64 + (lid & 15);
    int lrB = wn * 32 + ((lid >> 4) << 3) + (lid & 7);
    int ksA = lid >> 4, ksB = (lid >> 3) & 1;
    uint32_t Abase = A_addr + (uint32_t)(lrA * 512);
    uint32_t Bbase = (diag ? A_addr : B_addr) + (uint32_t)(lrB * 512);
    int rA7 = lrA & 7, rB7 = lrB & 7;

    float acc[4][4][4];
    #pragma unroll
    for (int a = 0; a < 4; a++)
        #pragma unroll
        for (int b = 0; b < 4; b++)
            #pragma unroll
            for (int cc = 0; cc < 4; cc++) acc[a][b][cc] = 0.0f;

    #pragma unroll
    for (int ks = 0; ks < 16; ks++) {
        uint32_t af[4][4], bf[2][4];
        uint32_t offA = (uint32_t)(((ks * 2 + ksA) ^ rA7) << 4);
        uint32_t offB = (uint32_t)(((ks * 2 + ksB) ^ rB7) << 4);
        #pragma unroll
        for (int mt = 0; mt < 4; mt++)
            LDSM4(af[mt], Abase + (uint32_t)(mt * 16 * 512) + offA);
        #pragma unroll
        for (int q = 0; q < 2; q++)
            LDSM4(bf[q], Bbase + (uint32_t)(q * 16 * 512) + offB);
        #pragma unroll
        for (int mt = 0; mt < 4; mt++) {
            MMA16816(acc[mt][0], af[mt], bf[0][0], bf[0][1]);
            MMA16816(acc[mt][1], af[mt], bf[0][2], bf[0][3]);
            MMA16816(acc[mt][2], af[mt], bf[1][0], bf[1][1]);
            MMA16816(acc[mt][3], af[mt], bf[1][2], bf[1][3]);
        }
    }

    // upper-triangle only (off-diag tiles always gi<gj; diag tiles full)
    #pragma unroll
    for (int mt = 0; mt < 4; mt++)
        #pragma unroll
        for (int half = 0; half < 2; half++) {
            int gi = ti * 128 + wm * 64 + mt * 16 + (lid >> 2) + half * 8;
            #pragma unroll
            for (int nt = 0; nt < 4; nt++)
                #pragma unroll
                for (int e = 0; e < 2; e++) {
                    int gj = tj * 128 + wn * 32 + nt * 8 + 2 * (lid & 3) + e;
                    atomicAdd(&g_G[gi * FF + gj], acc[mt][nt][half * 2 + e]);
                }
        }
}

// ------------------------- correlation matrix ---------------------------
__global__ void k_cor() {
    int i = blockIdx.x, j = threadIdx.x;
    int a = min(i, j), b = max(i, j);
    float mi = g_mean[i] / (float)NN;
    float mj = g_mean[j] / (float)NN;
    float cov = g_G[a * FF + b] - (float)NN * mi * mj;
    float vii = g_G[i * FF + i] - (float)NN * mi * mi;
    float vjj = g_G[j * FF + j] - (float)NN * mj * mj;
    float c = cov / (sqrtf(vii) * sqrtf(vjj));
    if (isnan(c)) c = 0.0f;
    c = fminf(fmaxf(c, -1.0f), 1.0f);
    if (i == j) c = 0.0f;
    g_cor[i * FF + j] = c;
    g_corb[i * FF + j] = __float2bfloat16(c);
}

// ------------------------- W = w * (z - mean) in bf16 -------------------
__global__ void k_wb(const float* __restrict__ z) {
    int t = blockIdx.x * blockDim.x + threadIdx.x;
    for (int idx = t; idx < NN * FF; idx += gridDim.x * blockDim.x) {
        int row = idx >> 8, col = idx & 255;
        float v = g_w[row] * (z[idx] - g_mean[col] / (float)NN);
        g_wb[idx] = __float2bfloat16(v);
    }
}

// ------------------------- z2 via HMMA: z + eps * (W @ cor) -> g_zb -----
__global__ __launch_bounds__(256, 1) void k_z2_mma(const float* __restrict__ z) {
    extern __shared__ char smem[];
    uint32_t raw = smem_addr_u32(smem);
    uint32_t base = (raw + 1023u) & ~1023u;
    char* sb = smem + (base - raw);
    uint32_t A_addr = base;
    uint32_t B_addr = base + 65536;
    char* A_ptr = sb;
    char* B_ptr = sb + 65536;

    int tid = threadIdx.x;
    int wid = tid >> 5, lid = tid & 31;

    int i0 = (blockIdx.x >> 1) * 128;
    int j0 = (blockIdx.x & 1) * 128;

    for (int idx = tid; idx < 4096; idx += 256) {
        int r = idx >> 5, g = idx & 31;
        uint32_t sw = (uint32_t)(r * 512 + ((g ^ (r & 7)) << 4));
        *(uint4*)(A_ptr + sw) = *(const uint4*)&g_wb[(i0 + r) * FF + g * 8];
        *(uint4*)(B_ptr + sw) = *(const uint4*)&g_corb[(j0 + r) * FF + g * 8];
    }
    __syncthreads();

    int wm = wid >> 2, wn = wid & 3;
    int lrA = wm * 64 + (lid & 15);
    int lrB = wn * 32 + ((lid >> 4) << 3) + (lid & 7);
    int ksA = lid >> 4, ksB = (lid >> 3) & 1;
    uint32_t Abase = A_addr + (uint32_t)(lrA * 512);
    uint32_t Bbase = B_addr + (uint32_t)(lrB * 512);
    int rA7 = lrA & 7, rB7 = lrB & 7;

    float acc[4][4][4];
    #pragma unroll
    for (int a = 0; a < 4; a++)
        #pragma unroll
        for (int b = 0; b < 4; b++)
            #pragma unroll
            for (int cc = 0; cc < 4; cc++) acc[a][b][cc] = 0.0f;

    #pragma unroll
    for (int ks = 0; ks < 16; ks++) {
        uint32_t af[4][4], bf[2][4];
        uint32_t offA = (uint32_t)(((ks * 2 + ksA) ^ rA7) << 4);
        uint32_t offB = (uint32_t)(((ks * 2 + ksB) ^ rB7) << 4);
        #pragma unroll
        for (int mt = 0; mt < 4; mt++)
            LDSM4(af[mt], Abase + (uint32_t)(mt * 16 * 512) + offA);
        #pragma unroll
        for (int q = 0; q < 2; q++)
            LDSM4(bf[q], Bbase + (uint32_t)(q * 16 * 512) + offB);
        #pragma unroll
        for (int mt = 0; mt < 4; mt++) {
            MMA16816(acc[mt][0], af[mt], bf[0][0], bf[0][1]);
            MMA16816(acc[mt][1], af[mt], bf[0][2], bf[0][3]);
            MMA16816(acc[mt][2], af[mt], bf[1][0], bf[1][1]);
            MMA16816(acc[mt][3], af[mt], bf[1][2], bf[1][3]);
        }
    }

    #pragma unroll
    for (int mt = 0; mt < 4; mt++)
        #pragma unroll
        for (int half = 0; half < 2; half++) {
            int gi = i0 + wm * 64 + mt * 16 + (lid >> 2) + half * 8;
            #pragma unroll
            for (int nt = 0; nt < 4; nt++)
                #pragma unroll
                for (int e = 0; e < 2; e++) {
                    int gj = j0 + wn * 32 + nt * 8 + 2 * (lid & 3) + e;
                    int idx = gi * FF + gj;
                    float v = z[idx] + C_EPS * acc[mt][nt][half * 2 + e];
                    g_zb[idx] = __float2bfloat16(v);
                }
        }
}

// ------------------------- per-node inverse norms (bf16 z2) -------------
__global__ void k_norms() {
    int warp = threadIdx.x >> 5, lane = threadIdx.x & 31;
    int row = blockIdx.x * 8 + warp;
    uint4 a = ((const uint4*)&g_zb[row * FF])[lane];
    float s = 0.0f;
    {
        float2 f;
        f = __bfloat1622float2(*(__nv_bfloat162*)&a.x); s += f.x * f.x + f.y * f.y;
        f = __bfloat1622float2(*(__nv_bfloat162*)&a.y); s += f.x * f.x + f.y * f.y;
        f = __bfloat1622float2(*(__nv_bfloat162*)&a.z); s += f.x * f.x + f.y * f.y;
        f = __bfloat1622float2(*(__nv_bfloat162*)&a.w); s += f.x * f.x + f.y * f.y;
    }
    s = warp_red(s);
    if (lane == 0) g_inorm[row] = 1.0f / fmaxf(sqrtf(s), C_COSEPS);
}

// ------------------------- homophily: warp per edge ---------------------
__device__ __forceinline__ float bdot(unsigned ua, unsigned ub) {
    float2 fa = __bfloat1622float2(*(__nv_bfloat162*)&ua);
    float2 fb = __bfloat1622float2(*(__nv_bfloat162*)&ub);
    return fa.x * fb.x + fa.y * fb.y;
}

__global__ void k_edge() {
    int warp = threadIdx.x >> 5, lane = threadIdx.x & 31;
    int e = blockIdx.x * 8 + warp;
    int i = g_ei[e], j = g_ej[e];
    const uint4* pi = (const uint4*)&g_zb[i * FF];
    const uint4* pj = (const uint4*)&g_zb[j * FF];
    uint4 a = pi[lane];
    uint4 b = pj[lane];
    float d = bdot(a.x, b.x) + bdot(a.y, b.y) + bdot(a.z, b.z) + bdot(a.w, b.w);
    d = warp_red(d);
    if (lane == 0) {
        float sim = d * g_inorm[i] * g_inorm[j];
        atomicAdd(&g_scores[i], sim);
    }
}

// ------- big masked GEMM: HMMA, cp.async double-buffered, occ 2 ---------
// Chunk = 64 K-cols (128 B/row). Buffers: A0,A1 @ 0/16K, B0,B1 @ 32K/48K.
static constexpr int BIG_SMEM = 1024 + 4 * 16384;

__device__ __forceinline__ void big_issue(uint32_t base, int i0, int j0,
                                          bool diag, int tid, int ch) {
    int s = ch & 1;
    uint32_t abuf = base + (uint32_t)(s * 16384);
    uint32_t bbuf = base + 32768u + (uint32_t)(s * 16384);
    #pragma unroll
    for (int it = 0; it < 4; it++) {
        int idx = tid + it * 256;
        int r = idx >> 3, g = idx & 7;
        uint32_t dst = abuf + (uint32_t)(r * 128 + (((g ^ (r & 7))) << 4));
        CP_ASYNC16(dst, &g_zb[(i0 + r) * FF + ch * 64 + g * 8]);
    }
    if (!diag) {
        #pragma unroll
        for (int it = 0; it < 4; it++) {
            int idx = tid + it * 256;
            int r = idx >> 3, g = idx & 7;
            uint32_t dst = bbuf + (uint32_t)(r * 128 + (((g ^ (r & 7))) << 4));
            CP_ASYNC16(dst, &g_zb[(j0 + r) * FF + ch * 64 + g * 8]);
        }
    }
    CP_COMMIT();
}

__global__ __launch_bounds__(256, 2) void k_big_mma() {
    extern __shared__ char smem[];
    uint32_t raw = smem_addr_u32(smem);
    uint32_t base = (raw + 1023u) & ~1023u;

    int tid = threadIdx.x;
    int wid = tid >> 5, lid = tid & 31;

    int p = blockIdx.x, ti = 0;
    while (p >= 64 - ti) { p -= 64 - ti; ti++; }
    int tj = ti + p;
    int i0 = ti * 128, j0 = tj * 128;
    bool diag = (ti == tj);

    int wm = wid >> 2, wn = wid & 3;
    int lrA = wm * 64 + (lid & 15);
    int lrB = wn * 32 + ((lid >> 4) << 3) + (lid & 7);
    int ksA = lid >> 4, ksB = (lid >> 3) & 1;
    int rA7 = lrA & 7, rB7 = lrB & 7;
    uint32_t Arow = (uint32_t)(lrA * 128);
    uint32_t Brow = (uint32_t)(lrB * 128) + (diag ? 0u : 32768u);

    float acc[4][4][4];
    #pragma unroll
    for (int a = 0; a < 4; a++)
        #pragma unroll
        for (int b = 0; b < 4; b++)
            #pragma unroll
            for (int cc = 0; cc < 4; cc++) acc[a][b][cc] = 0.0f;

    big_issue(base, i0, j0, diag, tid, 0);

    for (int ch = 0; ch < 4; ch++) {
        if (ch < 3) {
            big_issue(base, i0, j0, diag, tid, ch + 1);
            CP_WAIT(1);
        } else {
            CP_WAIT(0);
        }
        __syncthreads();

        uint32_t sb = (uint32_t)((ch & 1) * 16384);
        uint32_t Ab = base + sb + Arow;
        uint32_t Bb = base + sb + Brow;
        #pragma unroll
        for (int ks = 0; ks < 4; ks++) {
            uint32_t af[4][4], bf[2][4];
            uint32_t offA = (uint32_t)(((ks * 2 + ksA) ^ rA7) << 4);
            uint32_t offB = (uint32_t)(((ks * 2 + ksB) ^ rB7) << 4);
            #pragma unroll
            for (int mt = 0; mt < 4; mt++)
                LDSM4(af[mt], Ab + (uint32_t)(mt * 16 * 128) + offA);
            #pragma unroll
            for (int q = 0; q < 2; q++)
                LDSM4(bf[q], Bb + (uint32_t)(q * 16 * 128) + offB);
            #pragma unroll
            for (int mt = 0; mt < 4; mt++) {
                MMA16816(acc[mt][0], af[mt], bf[0][0], bf[0][1]);
                MMA16816(acc[mt][1], af[mt], bf[0][2], bf[0][3]);
                MMA16816(acc[mt][2], af[mt], bf[1][0], bf[1][1]);
                MMA16816(acc[mt][3], af[mt], bf[1][2], bf[1][3]);
            }
        }
        __syncthreads();
    }

    // masked thresholded accumulation (symmetry weighting)
    int jcol = (j0 + wn * 32) >> 5;
    float local = 0.0f;
    #pragma unroll
    for (int mt = 0; mt < 4; mt++)
        #pragma unroll
        for (int half = 0; half < 2; half++) {
            int gi = i0 + wm * 64 + mt * 16 + (lid >> 2) + half * 8;
            unsigned word = g_adj[gi * (NN / 32) + jcol];
            #pragma unroll
            for (int nt = 0; nt < 4; nt++)
                #pragma unroll
                for (int e = 0; e < 2; e++) {
                    int gj = j0 + wn * 32 + nt * 8 + 2 * (lid & 3) + e;
                    float cv = acc[mt][nt][half * 2 + e];
                    bool conn = (word >> (gj & 31)) & 1u;
                    float fac = diag ? ((gj > gi) ? 2.0f : ((gj == gi) ? 1.0f : 0.0f))
                                     : 2.0f;
                    if (!conn && cv > C_THRESH) local += cv * fac;
                }
        }
    local = warp_red(local);
    if (lid == 0) atomicAdd(&g_psum, (double)local);
}

// ------------------------- final reduction ------------------------------
__global__ void k_final(float* out) {
    __shared__ double red[256];
    int tid = threadIdx.x;
    double h = 0.0;
    for (int n = tid; n < NN; n += 256) {
        float d = g_deg[n];
        if (d == 0.0f) d = 1.0f;
        h += (double)g_scores[n] / (double)d;
    }
    red[tid] = h;
    __syncthreads();
    for (int s = 128; s; s >>= 1) {
        if (tid < s) red[tid] += red[tid + s];
        __syncthreads();
    }
    if (tid == 0) {
        double homo = -red[0] / (double)NN;
        double pen = g_psum / ((double)NN * (double)NN);
        out[0] = (float)(homo + pen);
    }
}

// ------------------------- host launch ----------------------------------
extern "C" void kernel_launch(void* const* d_in, const int* in_sizes, int n_in,
                              void* d_out, int out_size) {
    const float* z = nullptr;
    const void* edges = nullptr;
    const void* fk = nullptr;
    const void* fu = nullptr;
    int seen_nf = 0, seen_n = 0;
    for (int t = 0; t < n_in; t++) {
        if (in_sizes[t] == NN * FF) {
            if (seen_nf == 0) z = (const float*)d_in[t];
            seen_nf++;
        } else if (in_sizes[t] == 2 * EE) {
            edges = d_in[t];
        } else if (in_sizes[t] == NN) {
            if (seen_n == 0) fk = d_in[t];
            else if (seen_n == 1) fu = d_in[t];
            seen_n++;
        }
    }
    float* out = (float*)d_out;

    cudaFuncSetAttribute(k_gram_mma, cudaFuncAttributeMaxDynamicSharedMemorySize, GEMM_SMEM);
    cudaFuncSetAttribute(k_z2_mma,   cudaFuncAttributeMaxDynamicSharedMemorySize, GEMM_SMEM);
    cudaFuncSetAttribute(k_big_mma,  cudaFuncAttributeMaxDynamicSharedMemorySize, BIG_SMEM);

    k_zero<<<2048, 1024>>>(edges, fk, fu);
    k_convert<<<EE / 256, 256>>>(edges, fk, fu);
    k_trans<<<dim3(NN / 64, FF / 64), 256>>>(z);
    k_gram_mma<<<96, 256, GEMM_SMEM>>>();
    k_cor<<<FF, FF>>>();
    k_wb<<<1024, 256>>>(z);
    k_z2_mma<<<128, 256, GEMM_SMEM>>>(z);
    k_norms<<<NN / 8, 256>>>();
    k_edge<<<EE / 8, 256>>>();
    k_big_mma<<<64 * 65 / 2, 256, BIG_SMEM>>>();
    k_final<<<1, 256>>>(out);
    (void)out_size;
}

// round 13
// speedup vs baseline: 3.2745x; 1.0448x over previous
#include <cuda_runtime.h>
#include <cuda_bf16.h>
#include <cstdint>
#include <math.h>

static constexpr int NN = 8192;
static constexpr int FF = 256;
static constexpr int EE = 262144;
static constexpr float C_EPS    = 0.01f;
static constexpr float C_THRESH = 0.8f;
static constexpr float C_L2A    = -0.15200309344504995f;  // log2(0.9)

// ------------------------- device scratch (no runtime alloc allowed) -------
__device__ float          g_mean[FF];            // column sums
__device__ float          g_meann[FF];           // mean (= sum/N)
__device__ float          g_G[FF * FF];
__device__ __nv_bfloat16  g_corb[FF * FF];
__device__ float          g_w[NN];
__device__ __nv_bfloat16  g_zt[FF * NN];         // bf16 of z^T
__device__ __nv_bfloat16  g_zb[NN * FF];         // bf16 of z2
__device__ float          g_norm2[NN];
__device__ float          g_scores[NN];
__device__ float          g_deg[NN];
__device__ unsigned       g_adj[NN * NN / 32];   // 8 MB bitmask
__device__ int            g_ei[EE];
__device__ int            g_ej[EE];
__device__ double         g_psum;
__device__ int            g_flag_e, g_flag_k, g_flag_u;

__device__ __forceinline__ float warp_red(float v) {
    #pragma unroll
    for (int o = 16; o; o >>= 1) v += __shfl_xor_sync(0xffffffffu, v, o);
    return v;
}

__device__ __forceinline__ uint32_t smem_addr_u32(const void* p) {
    uint32_t a;
    asm("{ .reg .u64 t; cvta.to.shared.u64 t, %1; cvt.u32.u64 %0, t; }"
        : "=r"(a) : "l"(p));
    return a;
}

#define LDSM4(r, a)                                                         \
    asm volatile("ldmatrix.sync.aligned.m8n8.x4.shared.b16 "                \
                 "{%0, %1, %2, %3}, [%4];"                                  \
                 : "=r"((r)[0]), "=r"((r)[1]), "=r"((r)[2]), "=r"((r)[3])   \
                 : "r"(a))

#define MMA16816(d, a, b0, b1)                                              \
    asm volatile("mma.sync.aligned.m16n8k16.row.col.f32.bf16.bf16.f32 "     \
                 "{%0, %1, %2, %3}, {%4, %5, %6, %7}, {%8, %9}, "           \
                 "{%0, %1, %2, %3};"                                        \
                 : "+f"((d)[0]), "+f"((d)[1]), "+f"((d)[2]), "+f"((d)[3])   \
                 : "r"((a)[0]), "r"((a)[1]), "r"((a)[2]), "r"((a)[3]),      \
                   "r"(b0), "r"(b1))

#define CP_ASYNC16(dst, src)                                                \
    asm volatile("cp.async.cg.shared.global [%0], [%1], 16;"                \
                 :: "r"(dst), "l"(__cvta_generic_to_global(src)) : "memory")

#define CP_COMMIT()  asm volatile("cp.async.commit_group;" ::: "memory")
#define CP_WAIT(n)   asm volatile("cp.async.wait_group %0;" :: "n"(n) : "memory")

// ------------------------- dtype detection ------------------------------
__device__ __forceinline__ int detect64(const void* p, long long bound) {
    const long long* q = (const long long*)p;
    int c = 0;
    for (int s = 0; s < 64; s++) {
        long long v = q[s];
        if (v >= 0 && v < bound) c++;
    }
    return c >= 60 ? 1 : 0;
}

// ------------------------- zero + detect --------------------------------
__global__ void k_zero(const void* ep, const void* kp, const void* up) {
    int idx = blockIdx.x * blockDim.x + threadIdx.x;
    int stride = gridDim.x * blockDim.x;
    for (int i = idx; i < NN * NN / 32; i += stride) g_adj[i] = 0u;
    for (int i = idx; i < FF * FF; i += stride) g_G[i] = 0.0f;
    for (int i = idx; i < NN; i += stride) {
        g_scores[i] = 0.0f; g_deg[i] = 0.0f; g_norm2[i] = 0.0f;
    }
    for (int i = idx; i < FF; i += stride) g_mean[i] = 0.0f;
    if (idx == 0) {
        g_psum = 0.0;
        g_flag_e = detect64(ep, NN);
        g_flag_k = detect64(kp, 6);
        g_flag_u = detect64(up, 32);
    }
}

// --------------- edges + adjacency + degree + node weights --------------
__global__ void k_convert(const void* ep, const void* kp, const void* up) {
    int e = blockIdx.x * blockDim.x + threadIdx.x;
    if (e >= EE) return;
    int i, j;
    if (g_flag_e) {
        const long long* p = (const long long*)ep;
        i = (int)p[e]; j = (int)p[EE + e];
    } else {
        const int* p = (const int*)ep;
        i = p[e]; j = p[EE + e];
    }
    g_ei[e] = i;
    g_ej[e] = j;
    atomicOr(&g_adj[(i * NN + j) >> 5], 1u << (j & 31));
    atomicOr(&g_adj[(j * NN + i) >> 5], 1u << (i & 31));
    atomicAdd(&g_deg[i], 1.0f);

    if (e < NN) {
        float fk, fu;
        if (g_flag_k) fk = (float)((const long long*)kp)[e];
        else          fk = (float)((const int*)kp)[e];
        if (g_flag_u) fu = (float)((const long long*)up)[e];
        else          fu = (float)((const int*)up)[e];
        g_w[e] = exp2f(fk * C_L2A) + 1.0f - exp2f(fu * C_L2A);
    }
}

// --------------- transpose z -> g_zt (bf16) + column sums ---------------
__global__ void k_trans(const float* __restrict__ z) {
    __shared__ __nv_bfloat16 s[64][66];
    __shared__ float cs[64];
    int n0 = blockIdx.x * 64, f0 = blockIdx.y * 64;
    int tid = threadIdx.x;
    int c = tid & 63, r4 = tid >> 6;
    if (tid < 64) cs[tid] = 0.0f;
    __syncthreads();
    float acc = 0.0f;
    #pragma unroll
    for (int i = 0; i < 16; i++) {
        int r = r4 + i * 4;
        float v = z[(n0 + r) * FF + f0 + c];
        s[c][r] = __float2bfloat16(v);
        acc += v;
    }
    atomicAdd(&cs[c], acc);
    __syncthreads();
    #pragma unroll
    for (int i = 0; i < 16; i++) {
        int cc = r4 + i * 4;
        g_zt[(f0 + cc) * NN + n0 + c] = s[cc][c];
    }
    if (tid < 64) atomicAdd(&g_mean[f0 + tid], cs[tid]);
}

// -------------- Gram G = z^T z via HMMA, split-K 128, occ 2 -------------
// grid = 3 tile-pairs x 64 K-slices of 128 nodes. Tiles 128x128 bf16 (32 KB).
static constexpr int GRAM_SMEM = 1024 + 2 * 32768;

__global__ __launch_bounds__(256, 2) void k_gram_mma() {
    extern __shared__ char smem[];
    uint32_t raw = smem_addr_u32(smem);
    uint32_t base = (raw + 1023u) & ~1023u;
    uint32_t A_addr = base;
    uint32_t B_addr = base + 32768;

    int tid = threadIdx.x;
    int wid = tid >> 5, lid = tid & 31;

    int p = blockIdx.x % 3;
    int k0 = (blockIdx.x / 3) * 128;
    int ti = (p == 2) ? 1 : 0;
    int tj = (p == 0) ? 0 : 1;
    bool diag = (ti == tj);

    // cp.async fill: 2048 granules per tile (128 rows x 16 granules of 16B)
    #pragma unroll
    for (int it = 0; it < 8; it++) {
        int idx = tid + it * 256;
        int r = idx >> 4, g = idx & 15;
        uint32_t sw = (uint32_t)(r * 256 + ((g ^ (r & 7)) << 4));
        CP_ASYNC16(A_addr + sw, &g_zt[(ti * 128 + r) * NN + k0 + g * 8]);
        if (!diag)
            CP_ASYNC16(B_addr + sw, &g_zt[(tj * 128 + r) * NN + k0 + g * 8]);
    }
    CP_COMMIT();
    CP_WAIT(0);
    __syncthreads();

    int wm = wid >> 2, wn = wid & 3;
    int lrA = wm * 64 + (lid & 15);
    int lrB = wn * 32 + ((lid >> 4) << 3) + (lid & 7);
    int ksA = lid >> 4, ksB = (lid >> 3) & 1;
    uint32_t Abase = A_addr + (uint32_t)(lrA * 256);
    uint32_t Bbase = (diag ? A_addr : B_addr) + (uint32_t)(lrB * 256);
    int rA7 = lrA & 7, rB7 = lrB & 7;

    float acc[4][4][4];
    #pragma unroll
    for (int a = 0; a < 4; a++)
        #pragma unroll
        for (int b = 0; b < 4; b++)
            #pragma unroll
            for (int cc = 0; cc < 4; cc++) acc[a][b][cc] = 0.0f;

    #pragma unroll
    for (int ks = 0; ks < 8; ks++) {
        uint32_t af[4][4], bf[2][4];
        uint32_t offA = (uint32_t)(((ks * 2 + ksA) ^ rA7) << 4);
        uint32_t offB = (uint32_t)(((ks * 2 + ksB) ^ rB7) << 4);
        #pragma unroll
        for (int mt = 0; mt < 4; mt++)
            LDSM4(af[mt], Abase + (uint32_t)(mt * 16 * 256) + offA);
        #pragma unroll
        for (int q = 0; q < 2; q++)
            LDSM4(bf[q], Bbase + (uint32_t)(q * 16 * 256) + offB);
        #pragma unroll
        for (int mt = 0; mt < 4; mt++) {
            MMA16816(acc[mt][0], af[mt], bf[0][0], bf[0][1]);
            MMA16816(acc[mt][1], af[mt], bf[0][2], bf[0][3]);
            MMA16816(acc[mt][2], af[mt], bf[1][0], bf[1][1]);
            MMA16816(acc[mt][3], af[mt], bf[1][2], bf[1][3]);
        }
    }

    // upper-triangle only
    #pragma unroll
    for (int mt = 0; mt < 4; mt++)
        #pragma unroll
        for (int half = 0; half < 2; half++) {
            int gi = ti * 128 + wm * 64 + mt * 16 + (lid >> 2) + half * 8;
            #pragma unroll
            for (int nt = 0; nt < 4; nt++)
                #pragma unroll
                for (int e = 0; e < 2; e++) {
                    int gj = tj * 128 + wn * 32 + nt * 8 + 2 * (lid & 3) + e;
                    atomicAdd(&g_G[gi * FF + gj], acc[mt][nt][half * 2 + e]);
                }
        }
}

// ------------------------- correlation matrix (bf16) --------------------
__global__ void k_cor() {
    int i = blockIdx.x, j = threadIdx.x;
    int a = min(i, j), b = max(i, j);
    float mi = g_mean[i] / (float)NN;
    float mj = g_mean[j] / (float)NN;
    float cov = g_G[a * FF + b] - (float)NN * mi * mj;
    float vii = g_G[i * FF + i] - (float)NN * mi * mi;
    float vjj = g_G[j * FF + j] - (float)NN * mj * mj;
    float c = cov / (sqrtf(vii) * sqrtf(vjj));
    if (isnan(c)) c = 0.0f;
    c = fminf(fmaxf(c, -1.0f), 1.0f);
    if (i == j) c = 0.0f;
    g_corb[i * FF + j] = __float2bfloat16(c);
    if (j == i) g_meann[i] = mi;
}

// ---- z2 via HMMA: z + eps*((w*(z-mean)) @ cor) -> g_zb, + norm2 --------
// 64-row i-tiles: grid = 128 i-tiles x 2 j-tiles, smem 96 KB, occ 2.
// A-fill fuses the W = w*(z-mean) computation (reads z fp32 directly).
static constexpr int Z2_SMEM = 1024 + 32768 + 65536;

__global__ __launch_bounds__(256, 2) void k_z2_mma(const float* __restrict__ z) {
    extern __shared__ char smem[];
    uint32_t raw = smem_addr_u32(smem);
    uint32_t base = (raw + 1023u) & ~1023u;
    char* sb = smem + (base - raw);
    uint32_t A_addr = base;
    uint32_t B_addr = base + 32768;
    char* A_ptr = sb;

    int tid = threadIdx.x;
    int wid = tid >> 5, lid = tid & 31;

    int i0 = (blockIdx.x >> 1) * 64;
    int j0 = (blockIdx.x & 1) * 128;

    // B (cor tile) via cp.async: 4096 granules
    #pragma unroll
    for (int it = 0; it < 16; it++) {
        int idx = tid + it * 256;
        int r = idx >> 5, g = idx & 31;
        uint32_t sw = (uint32_t)(r * 512 + ((g ^ (r & 7)) << 4));
        CP_ASYNC16(B_addr + sw, &g_corb[(j0 + r) * FF + g * 8]);
    }
    CP_COMMIT();

    // A: fused W computation, 2048 granules (64 rows x 32 granules)
    #pragma unroll
    for (int it = 0; it < 8; it++) {
        int idx = tid + it * 256;
        int r = idx >> 5, g = idx & 31;
        int row = i0 + r;
        float wv = g_w[row];
        const float* zp = &z[row * FF + g * 8];
        float4 z0 = *(const float4*)zp;
        float4 z1 = *(const float4*)(zp + 4);
        const float* mp = &g_meann[g * 8];
        float4 m0 = *(const float4*)mp;
        float4 m1 = *(const float4*)(mp + 4);
        __nv_bfloat162 b0 = __float22bfloat162_rn(
            make_float2(wv * (z0.x - m0.x), wv * (z0.y - m0.y)));
        __nv_bfloat162 b1 = __float22bfloat162_rn(
            make_float2(wv * (z0.z - m0.z), wv * (z0.w - m0.w)));
        __nv_bfloat162 b2 = __float22bfloat162_rn(
            make_float2(wv * (z1.x - m1.x), wv * (z1.y - m1.y)));
        __nv_bfloat162 b3 = __float22bfloat162_rn(
            make_float2(wv * (z1.z - m1.z), wv * (z1.w - m1.w)));
        uint4 o;
        o.x = *(unsigned*)&b0; o.y = *(unsigned*)&b1;
        o.z = *(unsigned*)&b2; o.w = *(unsigned*)&b3;
        uint32_t sw = (uint32_t)(r * 512 + ((g ^ (r & 7)) << 4));
        *(uint4*)(A_ptr + sw) = o;
    }
    CP_WAIT(0);
    __syncthreads();

    int wm = wid >> 2, wn = wid & 3;     // wm: 2 x 32 rows, wn: 4 x 32 cols
    int lrA = wm * 32 + (lid & 15);
    int lrB = wn * 32 + ((lid >> 4) << 3) + (lid & 7);
    int ksA = lid >> 4, ksB = (lid >> 3) & 1;
    uint32_t Abase = A_addr + (uint32_t)(lrA * 512);
    uint32_t Bbase = B_addr + (uint32_t)(lrB * 512);
    int rA7 = lrA & 7, rB7 = lrB & 7;

    float acc[2][4][4];
    #pragma unroll
    for (int a = 0; a < 2; a++)
        #pragma unroll
        for (int b = 0; b < 4; b++)
            #pragma unroll
            for (int cc = 0; cc < 4; cc++) acc[a][b][cc] = 0.0f;

    #pragma unroll
    for (int ks = 0; ks < 16; ks++) {
        uint32_t af[2][4], bf[2][4];
        uint32_t offA = (uint32_t)(((ks * 2 + ksA) ^ rA7) << 4);
        uint32_t offB = (uint32_t)(((ks * 2 + ksB) ^ rB7) << 4);
        #pragma unroll
        for (int mt = 0; mt < 2; mt++)
            LDSM4(af[mt], Abase + (uint32_t)(mt * 16 * 512) + offA);
        #pragma unroll
        for (int q = 0; q < 2; q++)
            LDSM4(bf[q], Bbase + (uint32_t)(q * 16 * 512) + offB);
        #pragma unroll
        for (int mt = 0; mt < 2; mt++) {
            MMA16816(acc[mt][0], af[mt], bf[0][0], bf[0][1]);
            MMA16816(acc[mt][1], af[mt], bf[0][2], bf[0][3]);
            MMA16816(acc[mt][2], af[mt], bf[1][0], bf[1][1]);
            MMA16816(acc[mt][3], af[mt], bf[1][2], bf[1][3]);
        }
    }

    // epilogue: z2 = z + eps*acc -> bf16 store + fused norm2 partials
    #pragma unroll
    for (int mt = 0; mt < 2; mt++)
        #pragma unroll
        for (int half = 0; half < 2; half++) {
            int gi = i0 + wm * 32 + mt * 16 + (lid >> 2) + half * 8;
            float s2 = 0.0f;
            #pragma unroll
            for (int nt = 0; nt < 4; nt++)
                #pragma unroll
                for (int e = 0; e < 2; e++) {
                    int gj = j0 + wn * 32 + nt * 8 + 2 * (lid & 3) + e;
                    int idx = gi * FF + gj;
                    float v = z[idx] + C_EPS * acc[mt][nt][half * 2 + e];
                    g_zb[idx] = __float2bfloat16(v);
                    s2 += v * v;
                }
            s2 += __shfl_xor_sync(0xffffffffu, s2, 1);
            s2 += __shfl_xor_sync(0xffffffffu, s2, 2);
            if ((lid & 3) == 0) atomicAdd(&g_norm2[gi], s2);
        }
}

// ------------------------- homophily: warp per edge ---------------------
__device__ __forceinline__ float bdot(unsigned ua, unsigned ub) {
    float2 fa = __bfloat1622float2(*(__nv_bfloat162*)&ua);
    float2 fb = __bfloat1622float2(*(__nv_bfloat162*)&ub);
    return fa.x * fb.x + fa.y * fb.y;
}

__global__ void k_edge() {
    int warp = threadIdx.x >> 5, lane = threadIdx.x & 31;
    int e = blockIdx.x * 8 + warp;
    int i = g_ei[e], j = g_ej[e];
    const uint4* pi = (const uint4*)&g_zb[i * FF];
    const uint4* pj = (const uint4*)&g_zb[j * FF];
    uint4 a = pi[lane];
    uint4 b = pj[lane];
    float d = bdot(a.x, b.x) + bdot(a.y, b.y) + bdot(a.z, b.z) + bdot(a.w, b.w);
    d = warp_red(d);
    if (lane == 0) {
        float ni = rsqrtf(fmaxf(g_norm2[i], 1e-16f));
        float nj = rsqrtf(fmaxf(g_norm2[j], 1e-16f));
        atomicAdd(&g_scores[i], d * ni * nj);
    }
}

// ------- big masked GEMM: HMMA, cp.async double-buffered, occ 2 ---------
static constexpr int BIG_SMEM = 1024 + 4 * 16384;

__device__ __forceinline__ void big_issue(uint32_t base, int i0, int j0,
                                          bool diag, int tid, int ch) {
    int s = ch & 1;
    uint32_t abuf = base + (uint32_t)(s * 16384);
    uint32_t bbuf = base + 32768u + (uint32_t)(s * 16384);
    #pragma unroll
    for (int it = 0; it < 4; it++) {
        int idx = tid + it * 256;
        int r = idx >> 3, g = idx & 7;
        uint32_t dst = abuf + (uint32_t)(r * 128 + (((g ^ (r & 7))) << 4));
        CP_ASYNC16(dst, &g_zb[(i0 + r) * FF + ch * 64 + g * 8]);
    }
    if (!diag) {
        #pragma unroll
        for (int it = 0; it < 4; it++) {
            int idx = tid + it * 256;
            int r = idx >> 3, g = idx & 7;
            uint32_t dst = bbuf + (uint32_t)(r * 128 + (((g ^ (r & 7))) << 4));
            CP_ASYNC16(dst, &g_zb[(j0 + r) * FF + ch * 64 + g * 8]);
        }
    }
    CP_COMMIT();
}

__global__ __launch_bounds__(256, 2) void k_big_mma() {
    extern __shared__ char smem[];
    uint32_t raw = smem_addr_u32(smem);
    uint32_t base = (raw + 1023u) & ~1023u;

    int tid = threadIdx.x;
    int wid = tid >> 5, lid = tid & 31;

    int p = blockIdx.x, ti = 0;
    while (p >= 64 - ti) { p -= 64 - ti; ti++; }
    int tj = ti + p;
    int i0 = ti * 128, j0 = tj * 128;
    bool diag = (ti == tj);

    int wm = wid >> 2, wn = wid & 3;
    int lrA = wm * 64 + (lid & 15);
    int lrB = wn * 32 + ((lid >> 4) << 3) + (lid & 7);
    int ksA = lid >> 4, ksB = (lid >> 3) & 1;
    int rA7 = lrA & 7, rB7 = lrB & 7;
    uint32_t Arow = (uint32_t)(lrA * 128);
    uint32_t Brow = (uint32_t)(lrB * 128) + (diag ? 0u : 32768u);

    float acc[4][4][4];
    #pragma unroll
    for (int a = 0; a < 4; a++)
        #pragma unroll
        for (int b = 0; b < 4; b++)
            #pragma unroll
            for (int cc = 0; cc < 4; cc++) acc[a][b][cc] = 0.0f;

    big_issue(base, i0, j0, diag, tid, 0);

    for (int ch = 0; ch < 4; ch++) {
        if (ch < 3) {
            big_issue(base, i0, j0, diag, tid, ch + 1);
            CP_WAIT(1);
        } else {
            CP_WAIT(0);
        }
        __syncthreads();

        uint32_t sb = (uint32_t)((ch & 1) * 16384);
        uint32_t Ab = base + sb + Arow;
        uint32_t Bb = base + sb + Brow;
        #pragma unroll
        for (int ks = 0; ks < 4; ks++) {
            uint32_t af[4][4], bf[2][4];
            uint32_t offA = (uint32_t)(((ks * 2 + ksA) ^ rA7) << 4);
            uint32_t offB = (uint32_t)(((ks * 2 + ksB) ^ rB7) << 4);
            #pragma unroll
            for (int mt = 0; mt < 4; mt++)
                LDSM4(af[mt], Ab + (uint32_t)(mt * 16 * 128) + offA);
            #pragma unroll
            for (int q = 0; q < 2; q++)
                LDSM4(bf[q], Bb + (uint32_t)(q * 16 * 128) + offB);
            #pragma unroll
            for (int mt = 0; mt < 4; mt++) {
                MMA16816(acc[mt][0], af[mt], bf[0][0], bf[0][1]);
                MMA16816(acc[mt][1], af[mt], bf[0][2], bf[0][3]);
                MMA16816(acc[mt][2], af[mt], bf[1][0], bf[1][1]);
                MMA16816(acc[mt][3], af[mt], bf[1][2], bf[1][3]);
            }
        }
        __syncthreads();
    }

    int jcol = (j0 + wn * 32) >> 5;
    float local = 0.0f;
    #pragma unroll
    for (int mt = 0; mt < 4; mt++)
        #pragma unroll
        for (int half = 0; half < 2; half++) {
            int gi = i0 + wm * 64 + mt * 16 + (lid >> 2) + half * 8;
            unsigned word = g_adj[gi * (NN / 32) + jcol];
            #pragma unroll
            for (int nt = 0; nt < 4; nt++)
                #pragma unroll
                for (int e = 0; e < 2; e++) {
                    int gj = j0 + wn * 32 + nt * 8 + 2 * (lid & 3) + e;
                    float cv = acc[mt][nt][half * 2 + e];
                    bool conn = (word >> (gj & 31)) & 1u;
                    float fac = diag ? ((gj > gi) ? 2.0f : ((gj == gi) ? 1.0f : 0.0f))
                                     : 2.0f;
                    if (!conn && cv > C_THRESH) local += cv * fac;
                }
        }
    local = warp_red(local);
    if (lid == 0) atomicAdd(&g_psum, (double)local);
}

// ------------------------- final reduction ------------------------------
__global__ void k_final(float* out) {
    __shared__ double red[256];
    int tid = threadIdx.x;
    double h = 0.0;
    for (int n = tid; n < NN; n += 256) {
        float d = g_deg[n];
        if (d == 0.0f) d = 1.0f;
        h += (double)g_scores[n] / (double)d;
    }
    red[tid] = h;
    __syncthreads();
    for (int s = 128; s; s >>= 1) {
        if (tid < s) red[tid] += red[tid + s];
        __syncthreads();
    }
    if (tid == 0) {
        double homo = -red[0] / (double)NN;
        double pen = g_psum / ((double)NN * (double)NN);
        out[0] = (float)(homo + pen);
    }
}

// ------------------------- host launch ----------------------------------
extern "C" void kernel_launch(void* const* d_in, const int* in_sizes, int n_in,
                              void* d_out, int out_size) {
    const float* z = nullptr;
    const void* edges = nullptr;
    const void* fk = nullptr;
    const void* fu = nullptr;
    int seen_nf = 0, seen_n = 0;
    for (int t = 0; t < n_in; t++) {
        if (in_sizes[t] == NN * FF) {
            if (seen_nf == 0) z = (const float*)d_in[t];
            seen_nf++;
        } else if (in_sizes[t] == 2 * EE) {
            edges = d_in[t];
        } else if (in_sizes[t] == NN) {
            if (seen_n == 0) fk = d_in[t];
            else if (seen_n == 1) fu = d_in[t];
            seen_n++;
        }
    }
    float* out = (float*)d_out;

    cudaFuncSetAttribute(k_gram_mma, cudaFuncAttributeMaxDynamicSharedMemorySize, GRAM_SMEM);
    cudaFuncSetAttribute(k_z2_mma,   cudaFuncAttributeMaxDynamicSharedMemorySize, Z2_SMEM);
    cudaFuncSetAttribute(k_big_mma,  cudaFuncAttributeMaxDynamicSharedMemorySize, BIG_SMEM);

    k_zero<<<2048, 1024>>>(edges, fk, fu);
    k_convert<<<EE / 256, 256>>>(edges, fk, fu);
    k_trans<<<dim3(NN / 64, FF / 64), 256>>>(z);
    k_gram_mma<<<192, 256, GRAM_SMEM>>>();
    k_cor<<<FF, FF>>>();
    k_z2_mma<<<256, 256, Z2_SMEM>>>(z);
    k_edge<<<EE / 8, 256>>>();
    k_big_mma<<<64 * 65 / 2, 256, BIG_SMEM>>>();
    k_final<<<1, 256>>>(out);
    (void)out_size;
}